// round 1
// baseline (speedup 1.0000x reference)
#include <cuda_runtime.h>
#include <cuda_bf16.h>
#include <math.h>

#define BATCH 2
#define SEQ   2048
#define EMB   1024
#define HEADS 16
#define HDIM  64
#define FFDIM 4096
#define MROWS (BATCH * SEQ)   // 4096

// ----------------------------------------------------------------------------
// Scratch (device globals — no runtime allocation allowed)
// ----------------------------------------------------------------------------
__device__ float g_h  [MROWS * EMB];   // LN output (reused for LN1 and LN2)
__device__ float g_q  [MROWS * EMB];
__device__ float g_k  [MROWS * EMB];
__device__ float g_v  [MROWS * EMB];
__device__ float g_ctx[MROWS * EMB];
__device__ float g_x1 [MROWS * EMB];   // x + attn_out
__device__ float g_ff [MROWS * FFDIM]; // gelu(h@W1+b1)

// ----------------------------------------------------------------------------
// LayerNorm: one block per row, 256 threads, 1024 cols (1 float4 / thread)
// ----------------------------------------------------------------------------
__inline__ __device__ float warp_sum(float v) {
    #pragma unroll
    for (int o = 16; o > 0; o >>= 1) v += __shfl_xor_sync(0xffffffffu, v, o);
    return v;
}

__global__ void ln_kernel(const float* __restrict__ x,
                          const float* __restrict__ scale,
                          const float* __restrict__ shift,
                          float* __restrict__ out)
{
    __shared__ float ssum[8], ssq[8];
    int row = blockIdx.x;
    int t = threadIdx.x;              // 0..255
    const float4* xr = (const float4*)(x + (size_t)row * EMB);
    float4 v = xr[t];
    float s  = v.x + v.y + v.z + v.w;
    float sq = v.x * v.x + v.y * v.y + v.z * v.z + v.w * v.w;
    float ws  = warp_sum(s);
    float wsq = warp_sum(sq);
    int lane = t & 31, wid = t >> 5;
    if (lane == 0) { ssum[wid] = ws; ssq[wid] = wsq; }
    __syncthreads();
    float tot = 0.f, totsq = 0.f;
    #pragma unroll
    for (int i = 0; i < 8; i++) { tot += ssum[i]; totsq += ssq[i]; }
    float mean = tot * (1.0f / EMB);
    float var  = totsq * (1.0f / EMB) - mean * mean;
    float inv  = rsqrtf(var + 1e-5f);
    float4 sc = ((const float4*)scale)[t];
    float4 sh = ((const float4*)shift)[t];
    float4 o;
    o.x = sc.x * (v.x - mean) * inv + sh.x;
    o.y = sc.y * (v.y - mean) * inv + sh.y;
    o.z = sc.z * (v.z - mean) * inv + sh.z;
    o.w = sc.w * (v.w - mean) * inv + sh.w;
    ((float4*)(out + (size_t)row * EMB))[t] = o;
}

// ----------------------------------------------------------------------------
// SGEMM: C[M,N] = epi(A[M,K] @ B[K,N] + bias) + residual
// BM=BN=128, BK=8, 256 threads, 8x8 per thread
// ----------------------------------------------------------------------------
__device__ __forceinline__ float gelu_tanh(float x) {
    const float c = 0.7978845608028654f;
    float x3 = x * x * x;
    return 0.5f * x * (1.0f + tanhf(c * (x + 0.044715f * x3)));
}

__global__ void gemm_kernel(const float* __restrict__ A,
                            const float* __restrict__ Bm,
                            const float* __restrict__ bias,   // nullable
                            const float* __restrict__ res,    // nullable
                            float* __restrict__ C,
                            int Ndim, int Kdim, int do_gelu)
{
    __shared__ float As[8][128];
    __shared__ float Bs[8][128];
    int tid = threadIdx.x;
    int tx = tid & 15;          // 0..15 (N dir)
    int ty = tid >> 4;          // 0..15 (M dir)
    int brow = blockIdx.y * 128;
    int bcol = blockIdx.x * 128;

    float acc[8][8];
    #pragma unroll
    for (int i = 0; i < 8; i++)
        #pragma unroll
        for (int j = 0; j < 8; j++) acc[i][j] = 0.f;

    int arow = tid >> 1;            // 0..127
    int acol = (tid & 1) * 4;       // 0 or 4
    int brw  = tid >> 5;            // 0..7
    int bcl  = (tid & 31) * 4;      // 0..124

    const float* Aptr = A  + (size_t)(brow + arow) * Kdim + acol;
    const float* Bptr = Bm + (size_t)brw * Ndim + bcol + bcl;

    for (int k0 = 0; k0 < Kdim; k0 += 8) {
        float4 av = *(const float4*)Aptr;
        As[acol + 0][arow] = av.x;
        As[acol + 1][arow] = av.y;
        As[acol + 2][arow] = av.z;
        As[acol + 3][arow] = av.w;
        *(float4*)&Bs[brw][bcl] = *(const float4*)Bptr;
        __syncthreads();
        #pragma unroll
        for (int kk = 0; kk < 8; kk++) {
            float ra[8], rb[8];
            *(float4*)&ra[0] = *(const float4*)&As[kk][ty * 8];
            *(float4*)&ra[4] = *(const float4*)&As[kk][ty * 8 + 4];
            *(float4*)&rb[0] = *(const float4*)&Bs[kk][tx * 8];
            *(float4*)&rb[4] = *(const float4*)&Bs[kk][tx * 8 + 4];
            #pragma unroll
            for (int i = 0; i < 8; i++)
                #pragma unroll
                for (int j = 0; j < 8; j++)
                    acc[i][j] += ra[i] * rb[j];
        }
        __syncthreads();
        Aptr += 8;
        Bptr += (size_t)8 * Ndim;
    }

    #pragma unroll
    for (int i = 0; i < 8; i++) {
        int row = brow + ty * 8 + i;
        #pragma unroll
        for (int j = 0; j < 8; j += 4) {
            int col = bcol + tx * 8 + j;
            size_t idx = (size_t)row * Ndim + col;
            float4 v;
            v.x = acc[i][j + 0];
            v.y = acc[i][j + 1];
            v.z = acc[i][j + 2];
            v.w = acc[i][j + 3];
            if (bias) {
                v.x += bias[col + 0]; v.y += bias[col + 1];
                v.z += bias[col + 2]; v.w += bias[col + 3];
            }
            if (do_gelu) {
                v.x = gelu_tanh(v.x); v.y = gelu_tanh(v.y);
                v.z = gelu_tanh(v.z); v.w = gelu_tanh(v.w);
            }
            if (res) {
                const float4 r = *(const float4*)(res + idx);
                v.x += r.x; v.y += r.y; v.z += r.z; v.w += r.w;
            }
            *(float4*)(C + idx) = v;
        }
    }
}

// ----------------------------------------------------------------------------
// Causal flash attention, fp32. Grid: (B*H, S/64). 64 threads = 1 query row each.
// smem: K tile 16KB + V tile 16KB + scores (transposed, conflict-free) 16KB = 48KB
// ----------------------------------------------------------------------------
__global__ void attn_kernel(const float* __restrict__ q,
                            const float* __restrict__ k,
                            const float* __restrict__ v,
                            float* __restrict__ ctx)
{
    __shared__ float Ksh[64][64];
    __shared__ float Vsh[64][64];
    __shared__ float Ssh[64][64];   // Ssh[j][r]: transposed -> conflict-free
    int bh = blockIdx.x;            // 0..31
    int qb = blockIdx.y;            // 0..31
    int b = bh / HEADS, h = bh % HEADS;
    int r = threadIdx.x;            // 0..63
    int qg = qb * 64 + r;

    const float* qrow = q + ((size_t)(b * SEQ + qg)) * EMB + h * HDIM;
    float4 qreg[16];
    #pragma unroll
    for (int e = 0; e < 16; e++) qreg[e] = ((const float4*)qrow)[e];

    float4 oacc[16];
    #pragma unroll
    for (int e = 0; e < 16; e++) oacc[e] = make_float4(0.f, 0.f, 0.f, 0.f);

    float m = -INFINITY, l = 0.f;
    const float scale = 0.125f;     // 1/sqrt(64)

    for (int kt = 0; kt <= qb; kt++) {
        // cooperative K/V tile load: 64 rows x 16 float4
        for (int idx = r; idx < 64 * 16; idx += 64) {
            int row = idx >> 4, c4 = idx & 15;
            size_t base = ((size_t)(b * SEQ + kt * 64 + row)) * EMB + h * HDIM;
            ((float4*)&Ksh[row][0])[c4] = *(const float4*)(k + base + c4 * 4);
            ((float4*)&Vsh[row][0])[c4] = *(const float4*)(v + base + c4 * 4);
        }
        __syncthreads();

        int jmax = (kt == qb) ? r : 63;
        float tmax = -INFINITY;
        // pass 1: scores
        for (int j = 0; j <= jmax; j++) {
            const float4* krow = (const float4*)&Ksh[j][0];
            float s0 = 0.f, s1 = 0.f, s2 = 0.f, s3 = 0.f;
            #pragma unroll
            for (int e = 0; e < 16; e++) {
                float4 kv = krow[e];
                s0 += qreg[e].x * kv.x;
                s1 += qreg[e].y * kv.y;
                s2 += qreg[e].z * kv.z;
                s3 += qreg[e].w * kv.w;
            }
            float s = ((s0 + s1) + (s2 + s3)) * scale;
            Ssh[j][r] = s;
            tmax = fmaxf(tmax, s);
        }
        float mnew = fmaxf(m, tmax);
        float corr = __expf(m - mnew);     // exp(-inf)=0 on first tile
        l *= corr;
        #pragma unroll
        for (int e = 0; e < 16; e++) {
            oacc[e].x *= corr; oacc[e].y *= corr;
            oacc[e].z *= corr; oacc[e].w *= corr;
        }
        // pass 2: probs @ V
        for (int j = 0; j <= jmax; j++) {
            float p = __expf(Ssh[j][r] - mnew);
            l += p;
            const float4* vrow = (const float4*)&Vsh[j][0];
            #pragma unroll
            for (int e = 0; e < 16; e++) {
                float4 vv = vrow[e];
                oacc[e].x += p * vv.x; oacc[e].y += p * vv.y;
                oacc[e].z += p * vv.z; oacc[e].w += p * vv.w;
            }
        }
        m = mnew;
        __syncthreads();
    }

    float inv_l = 1.f / l;
    float* op = ctx + ((size_t)(b * SEQ + qg)) * EMB + h * HDIM;
    #pragma unroll
    for (int e = 0; e < 16; e++) {
        float4 o;
        o.x = oacc[e].x * inv_l; o.y = oacc[e].y * inv_l;
        o.z = oacc[e].z * inv_l; o.w = oacc[e].w * inv_l;
        ((float4*)op)[e] = o;
    }
}

// ----------------------------------------------------------------------------
// Launch
// ----------------------------------------------------------------------------
extern "C" void kernel_launch(void* const* d_in, const int* in_sizes, int n_in,
                              void* d_out, int out_size)
{
    const float* x    = (const float*)d_in[0];
    const float* Wq   = (const float*)d_in[1];
    const float* Wk   = (const float*)d_in[2];
    const float* Wv   = (const float*)d_in[3];
    const float* Wo   = (const float*)d_in[4];
    const float* bo   = (const float*)d_in[5];
    const float* W1   = (const float*)d_in[6];
    const float* b1   = (const float*)d_in[7];
    const float* W2   = (const float*)d_in[8];
    const float* b2   = (const float*)d_in[9];
    const float* ln1s = (const float*)d_in[10];
    const float* ln1b = (const float*)d_in[11];
    const float* ln2s = (const float*)d_in[12];
    const float* ln2b = (const float*)d_in[13];
    float* out = (float*)d_out;

    float *h_p, *q_p, *k_p, *v_p, *ctx_p, *x1_p, *ff_p;
    cudaGetSymbolAddress((void**)&h_p,   g_h);
    cudaGetSymbolAddress((void**)&q_p,   g_q);
    cudaGetSymbolAddress((void**)&k_p,   g_k);
    cudaGetSymbolAddress((void**)&v_p,   g_v);
    cudaGetSymbolAddress((void**)&ctx_p, g_ctx);
    cudaGetSymbolAddress((void**)&x1_p,  g_x1);
    cudaGetSymbolAddress((void**)&ff_p,  g_ff);

    dim3 gemm_block(256);
    dim3 grid_1024(EMB / 128, MROWS / 128);    // N=1024
    dim3 grid_4096(FFDIM / 128, MROWS / 128);  // N=4096

    // 1) LN1
    ln_kernel<<<MROWS, 256>>>(x, ln1s, ln1b, h_p);

    // 2) QKV projections
    gemm_kernel<<<grid_1024, gemm_block>>>(h_p, Wq, nullptr, nullptr, q_p, EMB, EMB, 0);
    gemm_kernel<<<grid_1024, gemm_block>>>(h_p, Wk, nullptr, nullptr, k_p, EMB, EMB, 0);
    gemm_kernel<<<grid_1024, gemm_block>>>(h_p, Wv, nullptr, nullptr, v_p, EMB, EMB, 0);

    // 3) causal attention
    dim3 attn_grid(BATCH * HEADS, SEQ / 64);
    attn_kernel<<<attn_grid, 64>>>(q_p, k_p, v_p, ctx_p);

    // 4) x1 = x + ctx @ Wo + bo
    gemm_kernel<<<grid_1024, gemm_block>>>(ctx_p, Wo, bo, x, x1_p, EMB, EMB, 0);

    // 5) LN2
    ln_kernel<<<MROWS, 256>>>(x1_p, ln2s, ln2b, h_p);

    // 6) ff = gelu(h @ W1 + b1)
    gemm_kernel<<<grid_4096, gemm_block>>>(h_p, W1, b1, nullptr, ff_p, FFDIM, EMB, 1);

    // 7) out = x1 + ff @ W2 + b2
    gemm_kernel<<<grid_1024, gemm_block>>>(ff_p, W2, b2, x1_p, out, EMB, FFDIM, 0);
}

// round 3
// speedup vs baseline: 2.0380x; 2.0380x over previous
#include <cuda_runtime.h>
#include <cuda_bf16.h>
#include <math.h>
#include <stdint.h>

#define BATCH 2
#define SEQ   2048
#define EMB   1024
#define HEADS 16
#define HDIM  64
#define FFDIM 4096
#define MROWS (BATCH * SEQ)   // 4096
#define QKVN  (3 * EMB)       // 3072

// ----------------------------------------------------------------------------
// Scratch (device globals — no runtime allocation allowed)
// ----------------------------------------------------------------------------
__device__ float g_h   [MROWS * EMB];
__device__ float g_qkv [MROWS * QKVN];
__device__ float g_ctx [MROWS * EMB];
__device__ float g_x1  [MROWS * EMB];
__device__ float g_ff  [MROWS * FFDIM];
__device__ float g_wqkv[EMB * QKVN];    // [K=1024, N=3072] packed, tf32-rounded
__device__ float g_wo  [EMB * EMB];
__device__ float g_w1  [EMB * FFDIM];
__device__ float g_w2  [FFDIM * EMB];

// ----------------------------------------------------------------------------
// Helpers
// ----------------------------------------------------------------------------
__device__ __forceinline__ uint32_t smem_u32(const void* p) {
    uint32_t a;
    asm("{ .reg .u64 t; cvta.to.shared.u64 t, %1; cvt.u32.u64 %0, t; }" : "=r"(a) : "l"(p));
    return a;
}
__device__ __forceinline__ float rtf32(float x) {
    float r; asm("cvt.rna.tf32.f32 %0, %1;" : "=f"(r) : "f"(x)); return r;
}
__device__ __forceinline__ void cp16(void* dst, const void* src) {
    asm volatile("cp.async.cg.shared.global [%0], [%1], 16;"
                 :: "r"(smem_u32(dst)), "l"(src) : "memory");
}
__device__ __forceinline__ float gelu_tanh(float x) {
    const float c = 0.7978845608028654f;
    return 0.5f * x * (1.0f + tanhf(c * (x + 0.044715f * x * x * x)));
}
__device__ __forceinline__ void mma8(float* c, const uint32_t* a, const uint32_t* b) {
    asm volatile(
        "mma.sync.aligned.m16n8k8.row.col.f32.tf32.tf32.f32 "
        "{%0,%1,%2,%3}, {%4,%5,%6,%7}, {%8,%9}, {%0,%1,%2,%3};"
        : "+f"(c[0]), "+f"(c[1]), "+f"(c[2]), "+f"(c[3])
        : "r"(a[0]), "r"(a[1]), "r"(a[2]), "r"(a[3]), "r"(b[0]), "r"(b[1]));
}

// ----------------------------------------------------------------------------
// LayerNorm (rounds output to tf32 — feeds MMA A-side)
// ----------------------------------------------------------------------------
__inline__ __device__ float warp_sum(float v) {
    #pragma unroll
    for (int o = 16; o > 0; o >>= 1) v += __shfl_xor_sync(0xffffffffu, v, o);
    return v;
}
__global__ void ln_kernel(const float* __restrict__ x,
                          const float* __restrict__ scale,
                          const float* __restrict__ shift,
                          float* __restrict__ out)
{
    __shared__ float ssum[8], ssq[8];
    int row = blockIdx.x;
    int t = threadIdx.x;
    const float4* xr = (const float4*)(x + (size_t)row * EMB);
    float4 v = xr[t];
    float s  = v.x + v.y + v.z + v.w;
    float sq = v.x * v.x + v.y * v.y + v.z * v.z + v.w * v.w;
    float ws  = warp_sum(s);
    float wsq = warp_sum(sq);
    int lane = t & 31, wid = t >> 5;
    if (lane == 0) { ssum[wid] = ws; ssq[wid] = wsq; }
    __syncthreads();
    float tot = 0.f, totsq = 0.f;
    #pragma unroll
    for (int i = 0; i < 8; i++) { tot += ssum[i]; totsq += ssq[i]; }
    float mean = tot * (1.0f / EMB);
    float var  = totsq * (1.0f / EMB) - mean * mean;
    float inv  = rsqrtf(var + 1e-5f);
    float4 sc = ((const float4*)scale)[t];
    float4 sh = ((const float4*)shift)[t];
    float4 o;
    o.x = rtf32(sc.x * (v.x - mean) * inv + sh.x);
    o.y = rtf32(sc.y * (v.y - mean) * inv + sh.y);
    o.z = rtf32(sc.z * (v.z - mean) * inv + sh.z);
    o.w = rtf32(sc.w * (v.w - mean) * inv + sh.w);
    ((float4*)(out + (size_t)row * EMB))[t] = o;
}

// ----------------------------------------------------------------------------
// Weight prep: tf32 round (and QKV pack)
// ----------------------------------------------------------------------------
__global__ void round_copy(const float* __restrict__ in, float* __restrict__ out, int n)
{
    int i = (blockIdx.x * blockDim.x + threadIdx.x) * 4;
    if (i < n) {
        float4 v = *(const float4*)(in + i);
        v.x = rtf32(v.x); v.y = rtf32(v.y); v.z = rtf32(v.z); v.w = rtf32(v.w);
        *(float4*)(out + i) = v;
    }
}
__global__ void pack_qkv(const float* __restrict__ Wq, const float* __restrict__ Wk,
                         const float* __restrict__ Wv, float* __restrict__ out)
{
    int i = (blockIdx.x * blockDim.x + threadIdx.x) * 4;   // over EMB*EMB
    int k = i >> 10;            // /1024
    int n = i & 1023;
    float4 a = *(const float4*)(Wq + i);
    float4 b = *(const float4*)(Wk + i);
    float4 c = *(const float4*)(Wv + i);
    a.x = rtf32(a.x); a.y = rtf32(a.y); a.z = rtf32(a.z); a.w = rtf32(a.w);
    b.x = rtf32(b.x); b.y = rtf32(b.y); b.z = rtf32(b.z); b.w = rtf32(b.w);
    c.x = rtf32(c.x); c.y = rtf32(c.y); c.z = rtf32(c.z); c.w = rtf32(c.w);
    float* o = out + (size_t)k * QKVN + n;
    *(float4*)(o)            = a;
    *(float4*)(o + EMB)      = b;
    *(float4*)(o + 2 * EMB)  = c;
}

// ----------------------------------------------------------------------------
// tf32 mma.sync GEMM: C[M,N] = epi(A[M,K] @ B[K,N] + bias) + res
// CTA 128x128, BK=32, 256 threads (8 warps, 4Mx2N), warp tile 32x64.
// flags: 1 = gelu, 2 = round output to tf32
// ----------------------------------------------------------------------------
#define BK 32
#define APITCH 36
#define BPITCH 136
#define A_STG (128 * APITCH)      // floats per A stage
#define B_STG (BK * BPITCH)
#define GEMM_SMEM ((2 * (A_STG + B_STG)) * 4)

__global__ void __launch_bounds__(256, 1)
gemm_mma(const float* __restrict__ A, const float* __restrict__ B,
         const float* __restrict__ bias, const float* __restrict__ res,
         float* __restrict__ C, int N, int K, int flags)
{
    extern __shared__ float sm[];
    float* As = sm;                  // [2][128][APITCH]
    float* Bs = sm + 2 * A_STG;      // [2][BK][BPITCH]

    const int tid  = threadIdx.x;
    const int lane = tid & 31;
    const int warp = tid >> 5;
    const int wm   = warp & 3;       // 0..3
    const int wn   = warp >> 2;      // 0..1
    const int brow = blockIdx.y * 128;
    const int bcol = blockIdx.x * 128;

    float acc[2][8][4];
    #pragma unroll
    for (int mt = 0; mt < 2; mt++)
        #pragma unroll
        for (int nt = 0; nt < 8; nt++)
            #pragma unroll
            for (int e = 0; e < 4; e++) acc[mt][nt][e] = 0.f;

    const int nk = K / BK;

    // stage loader
    auto load_stage = [&](int st, int k0) {
        float* as = As + st * A_STG;
        float* bs = Bs + st * B_STG;
        #pragma unroll
        for (int i = 0; i < 4; i++) {
            int ch  = tid + i * 256;        // 0..1023
            int row = ch >> 3, c = ch & 7;  // A: 128 rows x 8 chunks
            cp16(as + row * APITCH + c * 4, A + (size_t)(brow + row) * K + k0 + c * 4);
        }
        #pragma unroll
        for (int i = 0; i < 4; i++) {
            int ch  = tid + i * 256;
            int row = ch >> 5, c = ch & 31; // B: 32 rows x 32 chunks
            cp16(bs + row * BPITCH + c * 4, B + (size_t)(k0 + row) * N + bcol + c * 4);
        }
        asm volatile("cp.async.commit_group;" ::: "memory");
    };

    load_stage(0, 0);

    for (int kt = 0; kt < nk; kt++) {
        if (kt + 1 < nk) {
            load_stage((kt + 1) & 1, (kt + 1) * BK);
            asm volatile("cp.async.wait_group 1;" ::: "memory");
        } else {
            asm volatile("cp.async.wait_group 0;" ::: "memory");
        }
        __syncthreads();

        const float* as = As + (kt & 1) * A_STG + (wm * 32) * APITCH;
        const float* bs = Bs + (kt & 1) * B_STG + wn * 64;

        #pragma unroll
        for (int ks = 0; ks < BK / 8; ks++) {
            const int k = ks * 8;
            uint32_t af[2][4];
            #pragma unroll
            for (int mt = 0; mt < 2; mt++) {
                int r = mt * 16 + (lane >> 2);
                int c = k + (lane & 3);
                af[mt][0] = __float_as_uint(as[r * APITCH + c]);
                af[mt][1] = __float_as_uint(as[(r + 8) * APITCH + c]);
                af[mt][2] = __float_as_uint(as[r * APITCH + c + 4]);
                af[mt][3] = __float_as_uint(as[(r + 8) * APITCH + c + 4]);
            }
            uint32_t bf[8][2];
            #pragma unroll
            for (int nt = 0; nt < 8; nt++) {
                int n = nt * 8 + (lane >> 2);
                int kk = k + (lane & 3);
                bf[nt][0] = __float_as_uint(bs[kk * BPITCH + n]);
                bf[nt][1] = __float_as_uint(bs[(kk + 4) * BPITCH + n]);
            }
            #pragma unroll
            for (int mt = 0; mt < 2; mt++)
                #pragma unroll
                for (int nt = 0; nt < 8; nt++)
                    mma8(acc[mt][nt], af[mt], bf[nt]);
        }
        __syncthreads();
    }

    // ---------------- epilogue ----------------
    #pragma unroll
    for (int mt = 0; mt < 2; mt++) {
        int r0 = brow + wm * 32 + mt * 16 + (lane >> 2);
        #pragma unroll
        for (int nt = 0; nt < 8; nt++) {
            int col = bcol + wn * 64 + nt * 8 + (lane & 3) * 2;
            float v0 = acc[mt][nt][0], v1 = acc[mt][nt][1];
            float v2 = acc[mt][nt][2], v3 = acc[mt][nt][3];
            if (bias) {
                float b0 = __ldg(bias + col), b1 = __ldg(bias + col + 1);
                v0 += b0; v1 += b1; v2 += b0; v3 += b1;
            }
            if (flags & 1) {
                v0 = gelu_tanh(v0); v1 = gelu_tanh(v1);
                v2 = gelu_tanh(v2); v3 = gelu_tanh(v3);
            }
            if (flags & 2) {
                v0 = rtf32(v0); v1 = rtf32(v1); v2 = rtf32(v2); v3 = rtf32(v3);
            }
            size_t i0 = (size_t)r0 * N + col;
            size_t i1 = (size_t)(r0 + 8) * N + col;
            if (res) {
                float2 r0v = *(const float2*)(res + i0);
                float2 r1v = *(const float2*)(res + i1);
                v0 += r0v.x; v1 += r0v.y; v2 += r1v.x; v3 += r1v.y;
            }
            *(float2*)(C + i0) = make_float2(v0, v1);
            *(float2*)(C + i1) = make_float2(v2, v3);
        }
    }
}

// ----------------------------------------------------------------------------
// Causal flash attention, fp32; q/k/v packed in one buffer with row stride 3072
// ----------------------------------------------------------------------------
__global__ void attn_kernel(const float* __restrict__ qkv,
                            float* __restrict__ ctx)
{
    __shared__ float Ksh[64][64];
    __shared__ float Vsh[64][64];
    __shared__ float Ssh[64][64];
    int bh = blockIdx.x;
    int qb = blockIdx.y;
    int b = bh / HEADS, h = bh % HEADS;
    int r = threadIdx.x;
    int qg = qb * 64 + r;

    const float* qrow = qkv + ((size_t)(b * SEQ + qg)) * QKVN + h * HDIM;
    float4 qreg[16];
    #pragma unroll
    for (int e = 0; e < 16; e++) qreg[e] = ((const float4*)qrow)[e];

    float4 oacc[16];
    #pragma unroll
    for (int e = 0; e < 16; e++) oacc[e] = make_float4(0.f, 0.f, 0.f, 0.f);

    float m = -INFINITY, l = 0.f;
    const float scale = 0.125f;

    for (int kt = 0; kt <= qb; kt++) {
        for (int idx = r; idx < 64 * 16; idx += 64) {
            int row = idx >> 4, c4 = idx & 15;
            size_t base = ((size_t)(b * SEQ + kt * 64 + row)) * QKVN + h * HDIM;
            ((float4*)&Ksh[row][0])[c4] = *(const float4*)(qkv + base + EMB + c4 * 4);
            ((float4*)&Vsh[row][0])[c4] = *(const float4*)(qkv + base + 2 * EMB + c4 * 4);
        }
        __syncthreads();

        int jmax = (kt == qb) ? r : 63;
        float tmax = -INFINITY;
        for (int j = 0; j <= jmax; j++) {
            const float4* krow = (const float4*)&Ksh[j][0];
            float s0 = 0.f, s1 = 0.f, s2 = 0.f, s3 = 0.f;
            #pragma unroll
            for (int e = 0; e < 16; e++) {
                float4 kv = krow[e];
                s0 += qreg[e].x * kv.x;
                s1 += qreg[e].y * kv.y;
                s2 += qreg[e].z * kv.z;
                s3 += qreg[e].w * kv.w;
            }
            float s = ((s0 + s1) + (s2 + s3)) * scale;
            Ssh[j][r] = s;
            tmax = fmaxf(tmax, s);
        }
        float mnew = fmaxf(m, tmax);
        float corr = __expf(m - mnew);
        l *= corr;
        #pragma unroll
        for (int e = 0; e < 16; e++) {
            oacc[e].x *= corr; oacc[e].y *= corr;
            oacc[e].z *= corr; oacc[e].w *= corr;
        }
        for (int j = 0; j <= jmax; j++) {
            float p = __expf(Ssh[j][r] - mnew);
            l += p;
            const float4* vrow = (const float4*)&Vsh[j][0];
            #pragma unroll
            for (int e = 0; e < 16; e++) {
                float4 vv = vrow[e];
                oacc[e].x += p * vv.x; oacc[e].y += p * vv.y;
                oacc[e].z += p * vv.z; oacc[e].w += p * vv.w;
            }
        }
        m = mnew;
        __syncthreads();
    }

    float inv_l = 1.f / l;
    float* op = ctx + ((size_t)(b * SEQ + qg)) * EMB + h * HDIM;
    #pragma unroll
    for (int e = 0; e < 16; e++) {
        float4 o;
        o.x = rtf32(oacc[e].x * inv_l); o.y = rtf32(oacc[e].y * inv_l);
        o.z = rtf32(oacc[e].z * inv_l); o.w = rtf32(oacc[e].w * inv_l);
        ((float4*)op)[e] = o;
    }
}

// ----------------------------------------------------------------------------
// Launch
// ----------------------------------------------------------------------------
extern "C" void kernel_launch(void* const* d_in, const int* in_sizes, int n_in,
                              void* d_out, int out_size)
{
    const float* x    = (const float*)d_in[0];
    const float* Wq   = (const float*)d_in[1];
    const float* Wk   = (const float*)d_in[2];
    const float* Wv   = (const float*)d_in[3];
    const float* Wo   = (const float*)d_in[4];
    const float* bo   = (const float*)d_in[5];
    const float* W1   = (const float*)d_in[6];
    const float* b1   = (const float*)d_in[7];
    const float* W2   = (const float*)d_in[8];
    const float* b2   = (const float*)d_in[9];
    const float* ln1s = (const float*)d_in[10];
    const float* ln1b = (const float*)d_in[11];
    const float* ln2s = (const float*)d_in[12];
    const float* ln2b = (const float*)d_in[13];
    float* out = (float*)d_out;

    float *h_p, *qkv_p, *ctx_p, *x1_p, *ff_p, *wqkv_p, *wo_p, *w1_p, *w2_p;
    cudaGetSymbolAddress((void**)&h_p,    g_h);
    cudaGetSymbolAddress((void**)&qkv_p,  g_qkv);
    cudaGetSymbolAddress((void**)&ctx_p,  g_ctx);
    cudaGetSymbolAddress((void**)&x1_p,   g_x1);
    cudaGetSymbolAddress((void**)&ff_p,   g_ff);
    cudaGetSymbolAddress((void**)&wqkv_p, g_wqkv);
    cudaGetSymbolAddress((void**)&wo_p,   g_wo);
    cudaGetSymbolAddress((void**)&w1_p,   g_w1);
    cudaGetSymbolAddress((void**)&w2_p,   g_w2);

    cudaFuncSetAttribute(gemm_mma, cudaFuncAttributeMaxDynamicSharedMemorySize, GEMM_SMEM);

    // weight prep
    pack_qkv  <<<(EMB * EMB / 4 + 255) / 256, 256>>>(Wq, Wk, Wv, wqkv_p);
    round_copy<<<(EMB * EMB / 4 + 255) / 256, 256>>>(Wo, wo_p, EMB * EMB);
    round_copy<<<(EMB * FFDIM / 4 + 255) / 256, 256>>>(W1, w1_p, EMB * FFDIM);
    round_copy<<<(EMB * FFDIM / 4 + 255) / 256, 256>>>(W2, w2_p, FFDIM * EMB);

    // 1) LN1
    ln_kernel<<<MROWS, 256>>>(x, ln1s, ln1b, h_p);

    dim3 gqkv(QKVN / 128, MROWS / 128);    // (24, 32)
    dim3 g1024(EMB / 128, MROWS / 128);    // (8, 32)
    dim3 g4096(FFDIM / 128, MROWS / 128);  // (32, 32)

    // 2) fused QKV projection
    gemm_mma<<<gqkv, 256, GEMM_SMEM>>>(h_p, wqkv_p, nullptr, nullptr, qkv_p, QKVN, EMB, 0);

    // 3) causal attention
    dim3 attn_grid(BATCH * HEADS, SEQ / 64);
    attn_kernel<<<attn_grid, 64>>>(qkv_p, ctx_p);

    // 4) x1 = x + ctx @ Wo + bo
    gemm_mma<<<g1024, 256, GEMM_SMEM>>>(ctx_p, wo_p, bo, x, x1_p, EMB, EMB, 0);

    // 5) LN2
    ln_kernel<<<MROWS, 256>>>(x1_p, ln2s, ln2b, h_p);

    // 6) ff = round(gelu(h @ W1 + b1))
    gemm_mma<<<g4096, 256, GEMM_SMEM>>>(h_p, w1_p, b1, nullptr, ff_p, FFDIM, EMB, 3);

    // 7) out = x1 + ff @ W2 + b2
    gemm_mma<<<g1024, 256, GEMM_SMEM>>>(ff_p, w2_p, b2, x1_p, out, EMB, FFDIM, 0);
}

// round 4
// speedup vs baseline: 3.3965x; 1.6666x over previous
#include <cuda_runtime.h>
#include <cuda_bf16.h>
#include <math.h>
#include <stdint.h>

#define BATCH 2
#define SEQ   2048
#define EMB   1024
#define HEADS 16
#define HDIM  64
#define FFDIM 4096
#define MROWS (BATCH * SEQ)   // 4096
#define QKVN  (3 * EMB)       // 3072

// ----------------------------------------------------------------------------
// Scratch (device globals — no runtime allocation allowed)
// ----------------------------------------------------------------------------
__device__ float g_h   [MROWS * EMB];
__device__ float g_qkv [MROWS * QKVN];
__device__ float g_ctx [MROWS * EMB];
__device__ float g_x1  [MROWS * EMB];
__device__ float g_ff  [MROWS * FFDIM];
__device__ float g_wqkv[EMB * QKVN];
__device__ float g_wo  [EMB * EMB];
__device__ float g_w1  [EMB * FFDIM];
__device__ float g_w2  [FFDIM * EMB];

// ----------------------------------------------------------------------------
// Helpers
// ----------------------------------------------------------------------------
__device__ __forceinline__ uint32_t smem_u32(const void* p) {
    uint32_t a;
    asm("{ .reg .u64 t; cvta.to.shared.u64 t, %1; cvt.u32.u64 %0, t; }" : "=r"(a) : "l"(p));
    return a;
}
__device__ __forceinline__ float rtf32(float x) {
    float r; asm("cvt.rna.tf32.f32 %0, %1;" : "=f"(r) : "f"(x)); return r;
}
__device__ __forceinline__ void cp16(void* dst, const void* src) {
    asm volatile("cp.async.cg.shared.global [%0], [%1], 16;"
                 :: "r"(smem_u32(dst)), "l"(src) : "memory");
}
__device__ __forceinline__ float gelu_tanh(float x) {
    const float c = 0.7978845608028654f;
    return 0.5f * x * (1.0f + tanhf(c * (x + 0.044715f * x * x * x)));
}
__device__ __forceinline__ void mma8(float* c, const uint32_t* a, const uint32_t* b) {
    asm volatile(
        "mma.sync.aligned.m16n8k8.row.col.f32.tf32.tf32.f32 "
        "{%0,%1,%2,%3}, {%4,%5,%6,%7}, {%8,%9}, {%0,%1,%2,%3};"
        : "+f"(c[0]), "+f"(c[1]), "+f"(c[2]), "+f"(c[3])
        : "r"(a[0]), "r"(a[1]), "r"(a[2]), "r"(a[3]), "r"(b[0]), "r"(b[1]));
}

// ----------------------------------------------------------------------------
// LayerNorm (rounds output to tf32 — feeds MMA A-side)
// ----------------------------------------------------------------------------
__inline__ __device__ float warp_sum(float v) {
    #pragma unroll
    for (int o = 16; o > 0; o >>= 1) v += __shfl_xor_sync(0xffffffffu, v, o);
    return v;
}
__global__ void ln_kernel(const float* __restrict__ x,
                          const float* __restrict__ scale,
                          const float* __restrict__ shift,
                          float* __restrict__ out)
{
    __shared__ float ssum[8], ssq[8];
    int row = blockIdx.x;
    int t = threadIdx.x;
    const float4* xr = (const float4*)(x + (size_t)row * EMB);
    float4 v = xr[t];
    float s  = v.x + v.y + v.z + v.w;
    float sq = v.x * v.x + v.y * v.y + v.z * v.z + v.w * v.w;
    float ws  = warp_sum(s);
    float wsq = warp_sum(sq);
    int lane = t & 31, wid = t >> 5;
    if (lane == 0) { ssum[wid] = ws; ssq[wid] = wsq; }
    __syncthreads();
    float tot = 0.f, totsq = 0.f;
    #pragma unroll
    for (int i = 0; i < 8; i++) { tot += ssum[i]; totsq += ssq[i]; }
    float mean = tot * (1.0f / EMB);
    float var  = totsq * (1.0f / EMB) - mean * mean;
    float inv  = rsqrtf(var + 1e-5f);
    float4 sc = ((const float4*)scale)[t];
    float4 sh = ((const float4*)shift)[t];
    float4 o;
    o.x = rtf32(sc.x * (v.x - mean) * inv + sh.x);
    o.y = rtf32(sc.y * (v.y - mean) * inv + sh.y);
    o.z = rtf32(sc.z * (v.z - mean) * inv + sh.z);
    o.w = rtf32(sc.w * (v.w - mean) * inv + sh.w);
    ((float4*)(out + (size_t)row * EMB))[t] = o;
}

// ----------------------------------------------------------------------------
// Weight prep: tf32 round (and QKV pack)
// ----------------------------------------------------------------------------
__global__ void round_copy(const float* __restrict__ in, float* __restrict__ out, int n)
{
    int i = (blockIdx.x * blockDim.x + threadIdx.x) * 4;
    if (i < n) {
        float4 v = *(const float4*)(in + i);
        v.x = rtf32(v.x); v.y = rtf32(v.y); v.z = rtf32(v.z); v.w = rtf32(v.w);
        *(float4*)(out + i) = v;
    }
}
__global__ void pack_qkv(const float* __restrict__ Wq, const float* __restrict__ Wk,
                         const float* __restrict__ Wv, float* __restrict__ out)
{
    int i = (blockIdx.x * blockDim.x + threadIdx.x) * 4;
    int k = i >> 10;
    int n = i & 1023;
    float4 a = *(const float4*)(Wq + i);
    float4 b = *(const float4*)(Wk + i);
    float4 c = *(const float4*)(Wv + i);
    a.x = rtf32(a.x); a.y = rtf32(a.y); a.z = rtf32(a.z); a.w = rtf32(a.w);
    b.x = rtf32(b.x); b.y = rtf32(b.y); b.z = rtf32(b.z); b.w = rtf32(b.w);
    c.x = rtf32(c.x); c.y = rtf32(c.y); c.z = rtf32(c.z); c.w = rtf32(c.w);
    float* o = out + (size_t)k * QKVN + n;
    *(float4*)(o)            = a;
    *(float4*)(o + EMB)      = b;
    *(float4*)(o + 2 * EMB)  = c;
}

// ----------------------------------------------------------------------------
// tf32 mma.sync GEMM: C[M,N] = epi(A[M,K] @ B[K,N] + bias) + res
// ----------------------------------------------------------------------------
#define BK 32
#define APITCH 36
#define BPITCH 136
#define A_STG (128 * APITCH)
#define B_STG (BK * BPITCH)
#define GEMM_SMEM ((2 * (A_STG + B_STG)) * 4)

__global__ void __launch_bounds__(256, 1)
gemm_mma(const float* __restrict__ A, const float* __restrict__ B,
         const float* __restrict__ bias, const float* __restrict__ res,
         float* __restrict__ C, int N, int K, int flags)
{
    extern __shared__ float sm[];
    float* As = sm;
    float* Bs = sm + 2 * A_STG;

    const int tid  = threadIdx.x;
    const int lane = tid & 31;
    const int warp = tid >> 5;
    const int wm   = warp & 3;
    const int wn   = warp >> 2;
    const int brow = blockIdx.y * 128;
    const int bcol = blockIdx.x * 128;

    float acc[2][8][4];
    #pragma unroll
    for (int mt = 0; mt < 2; mt++)
        #pragma unroll
        for (int nt = 0; nt < 8; nt++)
            #pragma unroll
            for (int e = 0; e < 4; e++) acc[mt][nt][e] = 0.f;

    const int nk = K / BK;

    auto load_stage = [&](int st, int k0) {
        float* as = As + st * A_STG;
        float* bs = Bs + st * B_STG;
        #pragma unroll
        for (int i = 0; i < 4; i++) {
            int ch  = tid + i * 256;
            int row = ch >> 3, c = ch & 7;
            cp16(as + row * APITCH + c * 4, A + (size_t)(brow + row) * K + k0 + c * 4);
        }
        #pragma unroll
        for (int i = 0; i < 4; i++) {
            int ch  = tid + i * 256;
            int row = ch >> 5, c = ch & 31;
            cp16(bs + row * BPITCH + c * 4, B + (size_t)(k0 + row) * N + bcol + c * 4);
        }
        asm volatile("cp.async.commit_group;" ::: "memory");
    };

    load_stage(0, 0);

    for (int kt = 0; kt < nk; kt++) {
        if (kt + 1 < nk) {
            load_stage((kt + 1) & 1, (kt + 1) * BK);
            asm volatile("cp.async.wait_group 1;" ::: "memory");
        } else {
            asm volatile("cp.async.wait_group 0;" ::: "memory");
        }
        __syncthreads();

        const float* as = As + (kt & 1) * A_STG + (wm * 32) * APITCH;
        const float* bs = Bs + (kt & 1) * B_STG + wn * 64;

        #pragma unroll
        for (int ks = 0; ks < BK / 8; ks++) {
            const int k = ks * 8;
            uint32_t af[2][4];
            #pragma unroll
            for (int mt = 0; mt < 2; mt++) {
                int r = mt * 16 + (lane >> 2);
                int c = k + (lane & 3);
                af[mt][0] = __float_as_uint(as[r * APITCH + c]);
                af[mt][1] = __float_as_uint(as[(r + 8) * APITCH + c]);
                af[mt][2] = __float_as_uint(as[r * APITCH + c + 4]);
                af[mt][3] = __float_as_uint(as[(r + 8) * APITCH + c + 4]);
            }
            uint32_t bf[8][2];
            #pragma unroll
            for (int nt = 0; nt < 8; nt++) {
                int n = nt * 8 + (lane >> 2);
                int kk = k + (lane & 3);
                bf[nt][0] = __float_as_uint(bs[kk * BPITCH + n]);
                bf[nt][1] = __float_as_uint(bs[(kk + 4) * BPITCH + n]);
            }
            #pragma unroll
            for (int mt = 0; mt < 2; mt++)
                #pragma unroll
                for (int nt = 0; nt < 8; nt++)
                    mma8(acc[mt][nt], af[mt], bf[nt]);
        }
        __syncthreads();
    }

    #pragma unroll
    for (int mt = 0; mt < 2; mt++) {
        int r0 = brow + wm * 32 + mt * 16 + (lane >> 2);
        #pragma unroll
        for (int nt = 0; nt < 8; nt++) {
            int col = bcol + wn * 64 + nt * 8 + (lane & 3) * 2;
            float v0 = acc[mt][nt][0], v1 = acc[mt][nt][1];
            float v2 = acc[mt][nt][2], v3 = acc[mt][nt][3];
            if (bias) {
                float b0 = __ldg(bias + col), b1 = __ldg(bias + col + 1);
                v0 += b0; v1 += b1; v2 += b0; v3 += b1;
            }
            if (flags & 1) {
                v0 = gelu_tanh(v0); v1 = gelu_tanh(v1);
                v2 = gelu_tanh(v2); v3 = gelu_tanh(v3);
            }
            if (flags & 2) {
                v0 = rtf32(v0); v1 = rtf32(v1); v2 = rtf32(v2); v3 = rtf32(v3);
            }
            size_t i0 = (size_t)r0 * N + col;
            size_t i1 = (size_t)(r0 + 8) * N + col;
            if (res) {
                float2 r0v = *(const float2*)(res + i0);
                float2 r1v = *(const float2*)(res + i1);
                v0 += r0v.x; v1 += r0v.y; v2 += r1v.x; v3 += r1v.y;
            }
            *(float2*)(C + i0) = make_float2(v0, v1);
            *(float2*)(C + i1) = make_float2(v2, v3);
        }
    }
}

// ----------------------------------------------------------------------------
// Tensor-core causal flash attention (tf32 mma.sync)
// Block: (b,h) x 64-query tile; 128 threads = 4 warps, warp owns 16 q-rows.
// K pitch 68 (B-frag conflict-free), V pitch 72 (B-frag conflict-free).
// Q smem tile (pitch 68) is reused as the P staging tile (warp-private rows).
// K/V tiles double-buffered via cp.async.
// ----------------------------------------------------------------------------
#define KP 68
#define VP 72
#define Q_FLOATS (64 * KP)          // also P
#define K_FLOATS (64 * KP)
#define V_FLOATS (64 * VP)
#define ATTN_SMEM ((Q_FLOATS + 2 * K_FLOATS + 2 * V_FLOATS) * 4)

__global__ void __launch_bounds__(128, 2)
attn_mma(const float* __restrict__ qkv, float* __restrict__ ctx)
{
    extern __shared__ float smf[];
    float* Qsh = smf;                          // [64][KP] -> later P
    float* Ksh = smf + Q_FLOATS;               // [2][64][KP]
    float* Vsh = Ksh + 2 * K_FLOATS;           // [2][64][VP]

    const int bh = blockIdx.x;
    const int qb = blockIdx.y;
    const int b = bh >> 4, h = bh & 15;
    const int tid = threadIdx.x, lane = tid & 31, w = tid >> 5;
    const int g = lane >> 2, t = lane & 3;

    // stage Q tile
    const float* qbase = qkv + ((size_t)(b * SEQ + qb * 64)) * QKVN + h * HDIM;
    for (int i = tid; i < 64 * 16; i += 128) {
        int r = i >> 4, c = i & 15;
        *(float4*)&Qsh[r * KP + c * 4] = *(const float4*)(qbase + (size_t)r * QKVN + c * 4);
    }
    __syncthreads();

    // Q fragments (held all kernel)
    uint32_t qf[8][4];
    {
        const float* qs = Qsh + (w * 16) * KP;
        #pragma unroll
        for (int kc = 0; kc < 8; kc++) {
            int c = kc * 8 + t;
            qf[kc][0] = __float_as_uint(qs[g * KP + c]);
            qf[kc][1] = __float_as_uint(qs[(g + 8) * KP + c]);
            qf[kc][2] = __float_as_uint(qs[g * KP + c + 4]);
            qf[kc][3] = __float_as_uint(qs[(g + 8) * KP + c + 4]);
        }
    }
    __syncthreads();   // Qsh now free for P

    float oacc[8][4];
    #pragma unroll
    for (int nt = 0; nt < 8; nt++)
        #pragma unroll
        for (int e = 0; e < 4; e++) oacc[nt][e] = 0.f;

    float m_lo = -INFINITY, m_hi = -INFINITY, l_lo = 0.f, l_hi = 0.f;
    const float scale = 0.125f;

    auto load_kv = [&](int kt, int st) {
        const float* kb = qkv + ((size_t)(b * SEQ + kt * 64)) * QKVN + h * HDIM + EMB;
        const float* vb = kb + EMB;
        float* ks = Ksh + st * K_FLOATS;
        float* vs = Vsh + st * V_FLOATS;
        for (int i = tid; i < 64 * 16; i += 128) {
            int r = i >> 4, c = i & 15;
            cp16(&ks[r * KP + c * 4], kb + (size_t)r * QKVN + c * 4);
            cp16(&vs[r * VP + c * 4], vb + (size_t)r * QKVN + c * 4);
        }
        asm volatile("cp.async.commit_group;" ::: "memory");
    };

    load_kv(0, 0);

    float* Psh = Qsh + (w * 16) * KP;   // warp-private 16 rows

    for (int kt = 0; kt <= qb; kt++) {
        int st = kt & 1;
        if (kt < qb) {
            load_kv(kt + 1, st ^ 1);
            asm volatile("cp.async.wait_group 1;" ::: "memory");
        } else {
            asm volatile("cp.async.wait_group 0;" ::: "memory");
        }
        __syncthreads();

        const float* ks = Ksh + st * K_FLOATS;
        const float* vs = Vsh + st * V_FLOATS;

        // ---- S = Q @ K^T ----
        float sacc[8][4];
        #pragma unroll
        for (int nt = 0; nt < 8; nt++) {
            #pragma unroll
            for (int e = 0; e < 4; e++) sacc[nt][e] = 0.f;
            const float* kr = ks + (nt * 8 + g) * KP;
            #pragma unroll
            for (int kc = 0; kc < 8; kc++) {
                uint32_t bfr[2];
                bfr[0] = __float_as_uint(kr[kc * 8 + t]);
                bfr[1] = __float_as_uint(kr[kc * 8 + t + 4]);
                mma8(sacc[nt], qf[kc], bfr);
            }
        }

        // ---- scale + causal mask + row max ----
        float tl = -INFINITY, th = -INFINITY;
        const int row_lo = w * 16 + g;          // local row
        const int row_hi = row_lo + 8;
        #pragma unroll
        for (int nt = 0; nt < 8; nt++) {
            float s0 = sacc[nt][0] * scale;
            float s1 = sacc[nt][1] * scale;
            float s2 = sacc[nt][2] * scale;
            float s3 = sacc[nt][3] * scale;
            if (kt == qb) {
                int c0 = nt * 8 + t * 2, c1 = c0 + 1;
                if (c0 > row_lo) s0 = -INFINITY;
                if (c1 > row_lo) s1 = -INFINITY;
                if (c0 > row_hi) s2 = -INFINITY;
                if (c1 > row_hi) s3 = -INFINITY;
            }
            sacc[nt][0] = s0; sacc[nt][1] = s1; sacc[nt][2] = s2; sacc[nt][3] = s3;
            tl = fmaxf(tl, fmaxf(s0, s1));
            th = fmaxf(th, fmaxf(s2, s3));
        }
        tl = fmaxf(tl, __shfl_xor_sync(0xffffffffu, tl, 1));
        tl = fmaxf(tl, __shfl_xor_sync(0xffffffffu, tl, 2));
        th = fmaxf(th, __shfl_xor_sync(0xffffffffu, th, 1));
        th = fmaxf(th, __shfl_xor_sync(0xffffffffu, th, 2));

        float mn_lo = fmaxf(m_lo, tl);
        float mn_hi = fmaxf(m_hi, th);
        float c_lo = __expf(m_lo - mn_lo);
        float c_hi = __expf(m_hi - mn_hi);

        // ---- p = exp(s - m), store to Psh, accumulate l ----
        float sl = 0.f, sh2 = 0.f;
        #pragma unroll
        for (int nt = 0; nt < 8; nt++) {
            float p0 = __expf(sacc[nt][0] - mn_lo);
            float p1 = __expf(sacc[nt][1] - mn_lo);
            float p2 = __expf(sacc[nt][2] - mn_hi);
            float p3 = __expf(sacc[nt][3] - mn_hi);
            sl += p0 + p1; sh2 += p2 + p3;
            int c = nt * 8 + t * 2;
            Psh[g * KP + c]           = rtf32(p0);
            Psh[g * KP + c + 1]       = rtf32(p1);
            Psh[(g + 8) * KP + c]     = rtf32(p2);
            Psh[(g + 8) * KP + c + 1] = rtf32(p3);
        }
        sl  += __shfl_xor_sync(0xffffffffu, sl, 1);
        sl  += __shfl_xor_sync(0xffffffffu, sl, 2);
        sh2 += __shfl_xor_sync(0xffffffffu, sh2, 1);
        sh2 += __shfl_xor_sync(0xffffffffu, sh2, 2);
        l_lo = l_lo * c_lo + sl;
        l_hi = l_hi * c_hi + sh2;
        m_lo = mn_lo; m_hi = mn_hi;

        #pragma unroll
        for (int nt = 0; nt < 8; nt++) {
            oacc[nt][0] *= c_lo; oacc[nt][1] *= c_lo;
            oacc[nt][2] *= c_hi; oacc[nt][3] *= c_hi;
        }
        __syncwarp();

        // ---- O += P @ V ----
        #pragma unroll
        for (int kc = 0; kc < 8; kc++) {
            uint32_t pf[4];
            pf[0] = __float_as_uint(Psh[g * KP + kc * 8 + t]);
            pf[1] = __float_as_uint(Psh[(g + 8) * KP + kc * 8 + t]);
            pf[2] = __float_as_uint(Psh[g * KP + kc * 8 + t + 4]);
            pf[3] = __float_as_uint(Psh[(g + 8) * KP + kc * 8 + t + 4]);
            const float* v0 = vs + (kc * 8 + t) * VP;
            const float* v1 = vs + (kc * 8 + t + 4) * VP;
            #pragma unroll
            for (int nt = 0; nt < 8; nt++) {
                uint32_t bfr[2];
                bfr[0] = __float_as_uint(v0[nt * 8 + g]);
                bfr[1] = __float_as_uint(v1[nt * 8 + g]);
                mma8(oacc[nt], pf, bfr);
            }
        }
        __syncthreads();
    }

    // ---- finalize: O /= l, write ctx (tf32-rounded, feeds Wo GEMM) ----
    float inv_lo = 1.f / l_lo, inv_hi = 1.f / l_hi;
    float* ob = ctx + ((size_t)(b * SEQ + qb * 64 + w * 16)) * EMB + h * HDIM;
    #pragma unroll
    for (int nt = 0; nt < 8; nt++) {
        int c = nt * 8 + t * 2;
        float2 lo = make_float2(rtf32(oacc[nt][0] * inv_lo), rtf32(oacc[nt][1] * inv_lo));
        float2 hi = make_float2(rtf32(oacc[nt][2] * inv_hi), rtf32(oacc[nt][3] * inv_hi));
        *(float2*)(ob + (size_t)g * EMB + c)       = lo;
        *(float2*)(ob + (size_t)(g + 8) * EMB + c) = hi;
    }
}

// ----------------------------------------------------------------------------
// Launch
// ----------------------------------------------------------------------------
extern "C" void kernel_launch(void* const* d_in, const int* in_sizes, int n_in,
                              void* d_out, int out_size)
{
    const float* x    = (const float*)d_in[0];
    const float* Wq   = (const float*)d_in[1];
    const float* Wk   = (const float*)d_in[2];
    const float* Wv   = (const float*)d_in[3];
    const float* Wo   = (const float*)d_in[4];
    const float* bo   = (const float*)d_in[5];
    const float* W1   = (const float*)d_in[6];
    const float* b1   = (const float*)d_in[7];
    const float* W2   = (const float*)d_in[8];
    const float* b2   = (const float*)d_in[9];
    const float* ln1s = (const float*)d_in[10];
    const float* ln1b = (const float*)d_in[11];
    const float* ln2s = (const float*)d_in[12];
    const float* ln2b = (const float*)d_in[13];
    float* out = (float*)d_out;

    float *h_p, *qkv_p, *ctx_p, *x1_p, *ff_p, *wqkv_p, *wo_p, *w1_p, *w2_p;
    cudaGetSymbolAddress((void**)&h_p,    g_h);
    cudaGetSymbolAddress((void**)&qkv_p,  g_qkv);
    cudaGetSymbolAddress((void**)&ctx_p,  g_ctx);
    cudaGetSymbolAddress((void**)&x1_p,   g_x1);
    cudaGetSymbolAddress((void**)&ff_p,   g_ff);
    cudaGetSymbolAddress((void**)&wqkv_p, g_wqkv);
    cudaGetSymbolAddress((void**)&wo_p,   g_wo);
    cudaGetSymbolAddress((void**)&w1_p,   g_w1);
    cudaGetSymbolAddress((void**)&w2_p,   g_w2);

    cudaFuncSetAttribute(gemm_mma, cudaFuncAttributeMaxDynamicSharedMemorySize, GEMM_SMEM);
    cudaFuncSetAttribute(attn_mma, cudaFuncAttributeMaxDynamicSharedMemorySize, ATTN_SMEM);

    // weight prep
    pack_qkv  <<<(EMB * EMB / 4 + 255) / 256, 256>>>(Wq, Wk, Wv, wqkv_p);
    round_copy<<<(EMB * EMB / 4 + 255) / 256, 256>>>(Wo, wo_p, EMB * EMB);
    round_copy<<<(EMB * FFDIM / 4 + 255) / 256, 256>>>(W1, w1_p, EMB * FFDIM);
    round_copy<<<(EMB * FFDIM / 4 + 255) / 256, 256>>>(W2, w2_p, FFDIM * EMB);

    // 1) LN1
    ln_kernel<<<MROWS, 256>>>(x, ln1s, ln1b, h_p);

    dim3 gqkv(QKVN / 128, MROWS / 128);
    dim3 g1024(EMB / 128, MROWS / 128);
    dim3 g4096(FFDIM / 128, MROWS / 128);

    // 2) fused QKV projection (tf32-rounded: feeds attention mma)
    gemm_mma<<<gqkv, 256, GEMM_SMEM>>>(h_p, wqkv_p, nullptr, nullptr, qkv_p, QKVN, EMB, 2);

    // 3) causal attention (tensor cores)
    dim3 attn_grid(BATCH * HEADS, SEQ / 64);
    attn_mma<<<attn_grid, 128, ATTN_SMEM>>>(qkv_p, ctx_p);

    // 4) x1 = x + ctx @ Wo + bo
    gemm_mma<<<g1024, 256, GEMM_SMEM>>>(ctx_p, wo_p, bo, x, x1_p, EMB, EMB, 0);

    // 5) LN2
    ln_kernel<<<MROWS, 256>>>(x1_p, ln2s, ln2b, h_p);

    // 6) ff = round(gelu(h @ W1 + b1))
    gemm_mma<<<g4096, 256, GEMM_SMEM>>>(h_p, w1_p, b1, nullptr, ff_p, FFDIM, EMB, 3);

    // 7) out = x1 + ff @ W2 + b2
    gemm_mma<<<g1024, 256, GEMM_SMEM>>>(ff_p, w2_p, b2, x1_p, out, EMB, FFDIM, 0);
}

// round 6
// speedup vs baseline: 5.1088x; 1.5042x over previous
#include <cuda_runtime.h>
#include <cuda_fp16.h>
#include <math.h>
#include <stdint.h>

#define BATCH 2
#define SEQ   2048
#define EMB   1024
#define HEADS 16
#define HDIM  64
#define FFDIM 4096
#define MROWS (BATCH * SEQ)   // 4096
#define QKVN  (3 * EMB)       // 3072

// ----------------------------------------------------------------------------
// Scratch (device globals — no runtime allocation allowed)
// ----------------------------------------------------------------------------
__device__ __half g_h   [MROWS * EMB];
__device__ __half g_qkv [MROWS * QKVN];
__device__ __half g_ctx [MROWS * EMB];
__device__ float  g_x1  [MROWS * EMB];
__device__ __half g_ff  [MROWS * FFDIM];
__device__ __half g_wqkv[EMB * QKVN];
__device__ __half g_wo  [EMB * EMB];
__device__ __half g_w1  [EMB * FFDIM];
__device__ __half g_w2  [FFDIM * EMB];

// ----------------------------------------------------------------------------
// Helpers
// ----------------------------------------------------------------------------
__device__ __forceinline__ uint32_t smem_u32(const void* p) {
    uint32_t a;
    asm("{ .reg .u64 t; cvta.to.shared.u64 t, %1; cvt.u32.u64 %0, t; }" : "=r"(a) : "l"(p));
    return a;
}
__device__ __forceinline__ void cp16(void* dst, const void* src) {
    asm volatile("cp.async.cg.shared.global [%0], [%1], 16;"
                 :: "r"(smem_u32(dst)), "l"(src) : "memory");
}
__device__ __forceinline__ float gelu_tanh(float x) {
    const float c = 0.7978845608028654f;
    return 0.5f * x * (1.0f + tanhf(c * (x + 0.044715f * x * x * x)));
}
__device__ __forceinline__ void ldsm_x4(uint32_t* r, uint32_t addr) {
    asm volatile("ldmatrix.sync.aligned.m8n8.x4.shared.b16 {%0,%1,%2,%3}, [%4];"
                 : "=r"(r[0]), "=r"(r[1]), "=r"(r[2]), "=r"(r[3]) : "r"(addr));
}
__device__ __forceinline__ void ldsm_x4t(uint32_t* r, uint32_t addr) {
    asm volatile("ldmatrix.sync.aligned.m8n8.x4.trans.shared.b16 {%0,%1,%2,%3}, [%4];"
                 : "=r"(r[0]), "=r"(r[1]), "=r"(r[2]), "=r"(r[3]) : "r"(addr));
}
__device__ __forceinline__ void mma16(float* c, const uint32_t* a, const uint32_t* b) {
    asm volatile(
        "mma.sync.aligned.m16n8k16.row.col.f32.f16.f16.f32 "
        "{%0,%1,%2,%3}, {%4,%5,%6,%7}, {%8,%9}, {%0,%1,%2,%3};"
        : "+f"(c[0]), "+f"(c[1]), "+f"(c[2]), "+f"(c[3])
        : "r"(a[0]), "r"(a[1]), "r"(a[2]), "r"(a[3]), "r"(b[0]), "r"(b[1]));
}

// ----------------------------------------------------------------------------
// LayerNorm: fp32 in, fp16 out (feeds mma A-side)
// ----------------------------------------------------------------------------
__inline__ __device__ float warp_sum(float v) {
    #pragma unroll
    for (int o = 16; o > 0; o >>= 1) v += __shfl_xor_sync(0xffffffffu, v, o);
    return v;
}
__global__ void ln_kernel(const float* __restrict__ x,
                          const float* __restrict__ scale,
                          const float* __restrict__ shift,
                          __half* __restrict__ out)
{
    __shared__ float ssum[8], ssq[8];
    int row = blockIdx.x;
    int t = threadIdx.x;
    const float4* xr = (const float4*)(x + (size_t)row * EMB);
    float4 v = xr[t];
    float s  = v.x + v.y + v.z + v.w;
    float sq = v.x * v.x + v.y * v.y + v.z * v.z + v.w * v.w;
    float ws  = warp_sum(s);
    float wsq = warp_sum(sq);
    int lane = t & 31, wid = t >> 5;
    if (lane == 0) { ssum[wid] = ws; ssq[wid] = wsq; }
    __syncthreads();
    float tot = 0.f, totsq = 0.f;
    #pragma unroll
    for (int i = 0; i < 8; i++) { tot += ssum[i]; totsq += ssq[i]; }
    float mean = tot * (1.0f / EMB);
    float var  = totsq * (1.0f / EMB) - mean * mean;
    float inv  = rsqrtf(var + 1e-5f);
    float4 sc = ((const float4*)scale)[t];
    float4 sh = ((const float4*)shift)[t];
    __half* op = out + (size_t)row * EMB + t * 4;
    *(half2*)op       = __floats2half2_rn(sc.x * (v.x - mean) * inv + sh.x,
                                          sc.y * (v.y - mean) * inv + sh.y);
    *(half2*)(op + 2) = __floats2half2_rn(sc.z * (v.z - mean) * inv + sh.z,
                                          sc.w * (v.w - mean) * inv + sh.w);
}

// ----------------------------------------------------------------------------
// Weight prep: fp32 -> fp16 (and QKV pack)
// ----------------------------------------------------------------------------
__global__ void tohalf(const float* __restrict__ in, __half* __restrict__ out, int n)
{
    int i = (blockIdx.x * blockDim.x + threadIdx.x) * 8;
    if (i < n) {
        float4 a = *(const float4*)(in + i);
        float4 b = *(const float4*)(in + i + 4);
        half2 h0 = __floats2half2_rn(a.x, a.y);
        half2 h1 = __floats2half2_rn(a.z, a.w);
        half2 h2 = __floats2half2_rn(b.x, b.y);
        half2 h3 = __floats2half2_rn(b.z, b.w);
        uint4 u;
        u.x = *(uint32_t*)&h0; u.y = *(uint32_t*)&h1;
        u.z = *(uint32_t*)&h2; u.w = *(uint32_t*)&h3;
        *(uint4*)(out + i) = u;
    }
}
__global__ void pack_qkv_h(const float* __restrict__ Wq, const float* __restrict__ Wk,
                           const float* __restrict__ Wv, __half* __restrict__ out)
{
    int i = (blockIdx.x * blockDim.x + threadIdx.x) * 4;   // over EMB*EMB
    int k = i >> 10;
    int n = i & 1023;
    float4 a = *(const float4*)(Wq + i);
    float4 b = *(const float4*)(Wk + i);
    float4 c = *(const float4*)(Wv + i);
    __half* o = out + (size_t)k * QKVN + n;
    *(half2*)(o)               = __floats2half2_rn(a.x, a.y);
    *(half2*)(o + 2)           = __floats2half2_rn(a.z, a.w);
    *(half2*)(o + EMB)         = __floats2half2_rn(b.x, b.y);
    *(half2*)(o + EMB + 2)     = __floats2half2_rn(b.z, b.w);
    *(half2*)(o + 2 * EMB)     = __floats2half2_rn(c.x, c.y);
    *(half2*)(o + 2 * EMB + 2) = __floats2half2_rn(c.z, c.w);
}

// ----------------------------------------------------------------------------
// fp16 mma.sync GEMM: C[M,N] = epi(A[M,K] @ B[K,N] + bias) + res
// CTA 128x128, BK=32, 256 threads (8 warps, 4Mx2N), warp tile 32x64.
// flags: 1 = gelu, 2 = fp16 output
// ----------------------------------------------------------------------------
#define BK 32
#define AP 40
#define BPH 136
#define A_STGH (128 * AP)
#define B_STGH (BK * BPH)
#define GEMM_SMEM ((2 * (A_STGH + B_STGH)) * 2)

__global__ void __launch_bounds__(256, 1)
gemm_mma(const __half* __restrict__ A, const __half* __restrict__ B,
         const float* __restrict__ bias, const float* __restrict__ res,
         void* __restrict__ Cout, int N, int K, int flags)
{
    extern __shared__ __half smh[];
    __half* As = smh;
    __half* Bs = smh + 2 * A_STGH;

    const int tid  = threadIdx.x;
    const int lane = tid & 31;
    const int warp = tid >> 5;
    const int wm   = warp & 3;
    const int wn   = warp >> 2;
    const int brow = blockIdx.y * 128;
    const int bcol = blockIdx.x * 128;
    const int g = lane >> 2, t = lane & 3;

    float acc[2][8][4];
    #pragma unroll
    for (int mt = 0; mt < 2; mt++)
        #pragma unroll
        for (int nt = 0; nt < 8; nt++)
            #pragma unroll
            for (int e = 0; e < 4; e++) acc[mt][nt][e] = 0.f;

    const int nk = K / BK;

    auto load_stage = [&](int st, int k0) {
        __half* as = As + st * A_STGH;
        __half* bs = Bs + st * B_STGH;
        #pragma unroll
        for (int i = 0; i < 2; i++) {
            int ch  = tid + i * 256;
            int row = ch >> 2, c = ch & 3;
            cp16(as + row * AP + c * 8, A + (size_t)(brow + row) * K + k0 + c * 8);
        }
        #pragma unroll
        for (int i = 0; i < 2; i++) {
            int ch  = tid + i * 256;
            int row = ch >> 4, c = ch & 15;
            cp16(bs + row * BPH + c * 8, B + (size_t)(k0 + row) * N + bcol + c * 8);
        }
        asm volatile("cp.async.commit_group;" ::: "memory");
    };

    load_stage(0, 0);

    const int lr = lane & 15;
    const int lc = (lane >> 4) * 8;
    const int br = lane & 7;
    const int bseg = lane >> 3;

    for (int kt = 0; kt < nk; kt++) {
        if (kt + 1 < nk) {
            load_stage((kt + 1) & 1, (kt + 1) * BK);
            asm volatile("cp.async.wait_group 1;" ::: "memory");
        } else {
            asm volatile("cp.async.wait_group 0;" ::: "memory");
        }
        __syncthreads();

        const __half* as = As + (kt & 1) * A_STGH + (wm * 32) * AP;
        const __half* bs = Bs + (kt & 1) * B_STGH + wn * 64;

        #pragma unroll
        for (int ks = 0; ks < 2; ks++) {
            const int k = ks * 16;
            uint32_t af[2][4];
            #pragma unroll
            for (int mt = 0; mt < 2; mt++)
                ldsm_x4(af[mt], smem_u32(as + (mt * 16 + lr) * AP + k + lc));
            #pragma unroll
            for (int nb = 0; nb < 4; nb++) {
                uint32_t bf[4];
                ldsm_x4t(bf, smem_u32(bs + (k + (bseg & 1) * 8 + br) * BPH
                                         + nb * 16 + (bseg >> 1) * 8));
                #pragma unroll
                for (int mt = 0; mt < 2; mt++) {
                    mma16(acc[mt][nb * 2],     af[mt], bf);
                    mma16(acc[mt][nb * 2 + 1], af[mt], bf + 2);
                }
            }
        }
        __syncthreads();
    }

    // ---------------- epilogue ----------------
    #pragma unroll
    for (int mt = 0; mt < 2; mt++) {
        int r0 = brow + wm * 32 + mt * 16 + g;
        #pragma unroll
        for (int nt = 0; nt < 8; nt++) {
            int col = bcol + wn * 64 + nt * 8 + t * 2;
            float v0 = acc[mt][nt][0], v1 = acc[mt][nt][1];
            float v2 = acc[mt][nt][2], v3 = acc[mt][nt][3];
            if (bias) {
                float b0 = __ldg(bias + col), b1 = __ldg(bias + col + 1);
                v0 += b0; v1 += b1; v2 += b0; v3 += b1;
            }
            if (flags & 1) {
                v0 = gelu_tanh(v0); v1 = gelu_tanh(v1);
                v2 = gelu_tanh(v2); v3 = gelu_tanh(v3);
            }
            size_t i0 = (size_t)r0 * N + col;
            size_t i1 = (size_t)(r0 + 8) * N + col;
            if (res) {
                float2 r0v = *(const float2*)(res + i0);
                float2 r1v = *(const float2*)(res + i1);
                v0 += r0v.x; v1 += r0v.y; v2 += r1v.x; v3 += r1v.y;
            }
            if (flags & 2) {
                *(half2*)((__half*)Cout + i0) = __floats2half2_rn(v0, v1);
                *(half2*)((__half*)Cout + i1) = __floats2half2_rn(v2, v3);
            } else {
                *(float2*)((float*)Cout + i0) = make_float2(v0, v1);
                *(float2*)((float*)Cout + i1) = make_float2(v2, v3);
            }
        }
    }
}

// ----------------------------------------------------------------------------
// fp16 tensor-core causal flash attention
// ----------------------------------------------------------------------------
#define HP 72
#define TILE_H (64 * HP)
#define ATTN_SMEM (5 * TILE_H * 2)

__global__ void __launch_bounds__(128, 2)
attn_mma(const __half* __restrict__ qkv, __half* __restrict__ ctx)
{
    extern __shared__ __half smh[];
    __half* Qsh = smh;                    // [64][HP] -> later P
    __half* Ksh = smh + TILE_H;           // [2][64][HP]
    __half* Vsh = Ksh + 2 * TILE_H;       // [2][64][HP]

    const int bh = blockIdx.x;
    const int qb = blockIdx.y;
    const int b = bh >> 4, h = bh & 15;
    const int tid = threadIdx.x, lane = tid & 31, w = tid >> 5;
    const int g = lane >> 2, t = lane & 3;
    const int lr = lane & 15, lc = (lane >> 4) * 8;
    const int br = lane & 7, bseg = lane >> 3;

    // stage Q tile
    const __half* qbase = qkv + ((size_t)(b * SEQ + qb * 64)) * QKVN + h * HDIM;
    for (int i = tid; i < 64 * 8; i += 128) {
        int r = i >> 3, c = i & 7;
        *(uint4*)(Qsh + r * HP + c * 8) = *(const uint4*)(qbase + (size_t)r * QKVN + c * 8);
    }
    __syncthreads();

    // Q fragments (held all kernel): 4 k-steps
    uint32_t qf[4][4];
    #pragma unroll
    for (int kc = 0; kc < 4; kc++)
        ldsm_x4(qf[kc], smem_u32(Qsh + (w * 16 + lr) * HP + kc * 16 + lc));
    __syncthreads();   // Qsh now free for P

    float oacc[8][4];
    #pragma unroll
    for (int nt = 0; nt < 8; nt++)
        #pragma unroll
        for (int e = 0; e < 4; e++) oacc[nt][e] = 0.f;

    float m_lo = -INFINITY, m_hi = -INFINITY, l_lo = 0.f, l_hi = 0.f;
    const float scale = 0.125f;

    auto load_kv = [&](int kt, int st) {
        const __half* kb = qkv + ((size_t)(b * SEQ + kt * 64)) * QKVN + h * HDIM + EMB;
        const __half* vb = kb + EMB;
        __half* ks = Ksh + st * TILE_H;
        __half* vs = Vsh + st * TILE_H;
        for (int i = tid; i < 64 * 8; i += 128) {
            int r = i >> 3, c = i & 7;
            cp16(ks + r * HP + c * 8, kb + (size_t)r * QKVN + c * 8);
            cp16(vs + r * HP + c * 8, vb + (size_t)r * QKVN + c * 8);
        }
        asm volatile("cp.async.commit_group;" ::: "memory");
    };

    load_kv(0, 0);

    __half* Pw = Qsh + (w * 16) * HP;   // warp-private 16 rows

    for (int kt = 0; kt <= qb; kt++) {
        int st = kt & 1;
        if (kt < qb) {
            load_kv(kt + 1, st ^ 1);
            asm volatile("cp.async.wait_group 1;" ::: "memory");
        } else {
            asm volatile("cp.async.wait_group 0;" ::: "memory");
        }
        __syncthreads();

        const __half* ks = Ksh + st * TILE_H;
        const __half* vs = Vsh + st * TILE_H;

        // ---- S = Q @ K^T ----
        // K fragment: lane groups -> (n0,k0),(n0,k8),(n8,k0),(n8,k8) so that
        // register pairs {kf[0],kf[1]} / {kf[2],kf[3]} are correct B operands.
        float sacc[8][4];
        #pragma unroll
        for (int nt = 0; nt < 8; nt++)
            #pragma unroll
            for (int e = 0; e < 4; e++) sacc[nt][e] = 0.f;
        #pragma unroll
        for (int kc = 0; kc < 4; kc++) {
            #pragma unroll
            for (int nb = 0; nb < 4; nb++) {
                uint32_t kf[4];
                ldsm_x4(kf, smem_u32(ks + (nb * 16 + (bseg >> 1) * 8 + br) * HP
                                        + kc * 16 + (bseg & 1) * 8));
                mma16(sacc[nb * 2],     qf[kc], kf);
                mma16(sacc[nb * 2 + 1], qf[kc], kf + 2);
            }
        }

        // ---- scale + causal mask + row max ----
        float tl = -INFINITY, th = -INFINITY;
        const int row_lo = w * 16 + g;
        const int row_hi = row_lo + 8;
        #pragma unroll
        for (int nt = 0; nt < 8; nt++) {
            float s0 = sacc[nt][0] * scale;
            float s1 = sacc[nt][1] * scale;
            float s2 = sacc[nt][2] * scale;
            float s3 = sacc[nt][3] * scale;
            if (kt == qb) {
                int c0 = nt * 8 + t * 2, c1 = c0 + 1;
                if (c0 > row_lo) s0 = -INFINITY;
                if (c1 > row_lo) s1 = -INFINITY;
                if (c0 > row_hi) s2 = -INFINITY;
                if (c1 > row_hi) s3 = -INFINITY;
            }
            sacc[nt][0] = s0; sacc[nt][1] = s1; sacc[nt][2] = s2; sacc[nt][3] = s3;
            tl = fmaxf(tl, fmaxf(s0, s1));
            th = fmaxf(th, fmaxf(s2, s3));
        }
        tl = fmaxf(tl, __shfl_xor_sync(0xffffffffu, tl, 1));
        tl = fmaxf(tl, __shfl_xor_sync(0xffffffffu, tl, 2));
        th = fmaxf(th, __shfl_xor_sync(0xffffffffu, th, 1));
        th = fmaxf(th, __shfl_xor_sync(0xffffffffu, th, 2));

        float mn_lo = fmaxf(m_lo, tl);
        float mn_hi = fmaxf(m_hi, th);
        float c_lo = __expf(m_lo - mn_lo);
        float c_hi = __expf(m_hi - mn_hi);

        // ---- p = exp(s - m) -> fp16 Psh; accumulate l ----
        float sl = 0.f, sh2 = 0.f;
        #pragma unroll
        for (int nt = 0; nt < 8; nt++) {
            float p0 = __expf(sacc[nt][0] - mn_lo);
            float p1 = __expf(sacc[nt][1] - mn_lo);
            float p2 = __expf(sacc[nt][2] - mn_hi);
            float p3 = __expf(sacc[nt][3] - mn_hi);
            sl += p0 + p1; sh2 += p2 + p3;
            int c = nt * 8 + t * 2;
            *(half2*)&Pw[g * HP + c]       = __floats2half2_rn(p0, p1);
            *(half2*)&Pw[(g + 8) * HP + c] = __floats2half2_rn(p2, p3);
        }
        sl  += __shfl_xor_sync(0xffffffffu, sl, 1);
        sl  += __shfl_xor_sync(0xffffffffu, sl, 2);
        sh2 += __shfl_xor_sync(0xffffffffu, sh2, 1);
        sh2 += __shfl_xor_sync(0xffffffffu, sh2, 2);
        l_lo = l_lo * c_lo + sl;
        l_hi = l_hi * c_hi + sh2;
        m_lo = mn_lo; m_hi = mn_hi;

        #pragma unroll
        for (int nt = 0; nt < 8; nt++) {
            oacc[nt][0] *= c_lo; oacc[nt][1] *= c_lo;
            oacc[nt][2] *= c_hi; oacc[nt][3] *= c_hi;
        }
        __syncwarp();

        // ---- O += P @ V (V rows are k, trans ldmatrix) ----
        #pragma unroll
        for (int kc = 0; kc < 4; kc++) {
            uint32_t pf[4];
            ldsm_x4(pf, smem_u32(Pw + lr * HP + kc * 16 + lc));
            #pragma unroll
            for (int nb = 0; nb < 4; nb++) {
                uint32_t vf[4];
                ldsm_x4t(vf, smem_u32(vs + (kc * 16 + (bseg & 1) * 8 + br) * HP
                                         + nb * 16 + (bseg >> 1) * 8));
                mma16(oacc[nb * 2],     pf, vf);
                mma16(oacc[nb * 2 + 1], pf, vf + 2);
            }
        }
        __syncthreads();
    }

    // ---- finalize: O /= l, write ctx fp16 ----
    float inv_lo = 1.f / l_lo, inv_hi = 1.f / l_hi;
    __half* ob = ctx + ((size_t)(b * SEQ + qb * 64 + w * 16)) * EMB + h * HDIM;
    #pragma unroll
    for (int nt = 0; nt < 8; nt++) {
        int c = nt * 8 + t * 2;
        *(half2*)(ob + (size_t)g * EMB + c) =
            __floats2half2_rn(oacc[nt][0] * inv_lo, oacc[nt][1] * inv_lo);
        *(half2*)(ob + (size_t)(g + 8) * EMB + c) =
            __floats2half2_rn(oacc[nt][2] * inv_hi, oacc[nt][3] * inv_hi);
    }
}

// ----------------------------------------------------------------------------
// Launch
// ----------------------------------------------------------------------------
extern "C" void kernel_launch(void* const* d_in, const int* in_sizes, int n_in,
                              void* d_out, int out_size)
{
    const float* x    = (const float*)d_in[0];
    const float* Wq   = (const float*)d_in[1];
    const float* Wk   = (const float*)d_in[2];
    const float* Wv   = (const float*)d_in[3];
    const float* Wo   = (const float*)d_in[4];
    const float* bo   = (const float*)d_in[5];
    const float* W1   = (const float*)d_in[6];
    const float* b1   = (const float*)d_in[7];
    const float* W2   = (const float*)d_in[8];
    const float* b2   = (const float*)d_in[9];
    const float* ln1s = (const float*)d_in[10];
    const float* ln1b = (const float*)d_in[11];
    const float* ln2s = (const float*)d_in[12];
    const float* ln2b = (const float*)d_in[13];
    float* out = (float*)d_out;

    __half *h_p, *qkv_p, *ctx_p, *ff_p, *wqkv_p, *wo_p, *w1_p, *w2_p;
    float *x1_p;
    cudaGetSymbolAddress((void**)&h_p,    g_h);
    cudaGetSymbolAddress((void**)&qkv_p,  g_qkv);
    cudaGetSymbolAddress((void**)&ctx_p,  g_ctx);
    cudaGetSymbolAddress((void**)&x1_p,   g_x1);
    cudaGetSymbolAddress((void**)&ff_p,   g_ff);
    cudaGetSymbolAddress((void**)&wqkv_p, g_wqkv);
    cudaGetSymbolAddress((void**)&wo_p,   g_wo);
    cudaGetSymbolAddress((void**)&w1_p,   g_w1);
    cudaGetSymbolAddress((void**)&w2_p,   g_w2);

    cudaFuncSetAttribute(gemm_mma, cudaFuncAttributeMaxDynamicSharedMemorySize, GEMM_SMEM);
    cudaFuncSetAttribute(attn_mma, cudaFuncAttributeMaxDynamicSharedMemorySize, ATTN_SMEM);

    // weight prep (fp32 -> fp16)
    pack_qkv_h<<<(EMB * EMB / 4 + 255) / 256, 256>>>(Wq, Wk, Wv, wqkv_p);
    tohalf<<<(EMB * EMB / 8 + 255) / 256, 256>>>(Wo, wo_p, EMB * EMB);
    tohalf<<<(EMB * FFDIM / 8 + 255) / 256, 256>>>(W1, w1_p, EMB * FFDIM);
    tohalf<<<(EMB * FFDIM / 8 + 255) / 256, 256>>>(W2, w2_p, FFDIM * EMB);

    // 1) LN1 -> fp16
    ln_kernel<<<MROWS, 256>>>(x, ln1s, ln1b, h_p);

    dim3 gqkv(QKVN / 128, MROWS / 128);
    dim3 g1024(EMB / 128, MROWS / 128);
    dim3 g4096(FFDIM / 128, MROWS / 128);

    // 2) fused QKV projection -> fp16
    gemm_mma<<<gqkv, 256, GEMM_SMEM>>>(h_p, wqkv_p, nullptr, nullptr, qkv_p, QKVN, EMB, 2);

    // 3) causal attention (fp16 tensor cores) -> fp16 ctx
    dim3 attn_grid(BATCH * HEADS, SEQ / 64);
    attn_mma<<<attn_grid, 128, ATTN_SMEM>>>(qkv_p, ctx_p);

    // 4) x1 = x + ctx @ Wo + bo  (fp32 out)
    gemm_mma<<<g1024, 256, GEMM_SMEM>>>(ctx_p, wo_p, bo, x, x1_p, EMB, EMB, 0);

    // 5) LN2 -> fp16
    ln_kernel<<<MROWS, 256>>>(x1_p, ln2s, ln2b, h_p);

    // 6) ff = gelu(h @ W1 + b1) -> fp16
    gemm_mma<<<g4096, 256, GEMM_SMEM>>>(h_p, w1_p, b1, nullptr, ff_p, FFDIM, EMB, 3);

    // 7) out = x1 + ff @ W2 + b2  (fp32 out)
    gemm_mma<<<g1024, 256, GEMM_SMEM>>>(ff_p, w2_p, b2, x1_p, out, EMB, FFDIM, 0);
}

// round 7
// speedup vs baseline: 5.5472x; 1.0858x over previous
#include <cuda_runtime.h>
#include <cuda_fp16.h>
#include <math.h>
#include <stdint.h>

#define BATCH 2
#define SEQ   2048
#define EMB   1024
#define HEADS 16
#define HDIM  64
#define FFDIM 4096
#define MROWS (BATCH * SEQ)   // 4096
#define QKVN  (3 * EMB)       // 3072

// ----------------------------------------------------------------------------
// Scratch (device globals — no runtime allocation allowed)
// ----------------------------------------------------------------------------
__device__ __half g_h   [MROWS * EMB];
__device__ __half g_qkv [MROWS * QKVN];
__device__ __half g_ctx [MROWS * EMB];
__device__ float  g_x1  [MROWS * EMB];
__device__ __half g_ff  [MROWS * FFDIM];
__device__ __half g_wqkv[EMB * QKVN];
__device__ __half g_wo  [EMB * EMB];
__device__ __half g_w1  [EMB * FFDIM];
__device__ __half g_w2  [FFDIM * EMB];

// ----------------------------------------------------------------------------
// Helpers
// ----------------------------------------------------------------------------
__device__ __forceinline__ uint32_t smem_u32(const void* p) {
    uint32_t a;
    asm("{ .reg .u64 t; cvta.to.shared.u64 t, %1; cvt.u32.u64 %0, t; }" : "=r"(a) : "l"(p));
    return a;
}
__device__ __forceinline__ void cp16(void* dst, const void* src) {
    asm volatile("cp.async.cg.shared.global [%0], [%1], 16;"
                 :: "r"(smem_u32(dst)), "l"(src) : "memory");
}
__device__ __forceinline__ float gelu_tanh(float x) {
    const float c = 0.7978845608028654f;
    return 0.5f * x * (1.0f + tanhf(c * (x + 0.044715f * x * x * x)));
}
__device__ __forceinline__ void ldsm_x4(uint32_t* r, uint32_t addr) {
    asm volatile("ldmatrix.sync.aligned.m8n8.x4.shared.b16 {%0,%1,%2,%3}, [%4];"
                 : "=r"(r[0]), "=r"(r[1]), "=r"(r[2]), "=r"(r[3]) : "r"(addr));
}
__device__ __forceinline__ void ldsm_x4t(uint32_t* r, uint32_t addr) {
    asm volatile("ldmatrix.sync.aligned.m8n8.x4.trans.shared.b16 {%0,%1,%2,%3}, [%4];"
                 : "=r"(r[0]), "=r"(r[1]), "=r"(r[2]), "=r"(r[3]) : "r"(addr));
}
__device__ __forceinline__ void mma16(float* c, const uint32_t* a, const uint32_t* b) {
    asm volatile(
        "mma.sync.aligned.m16n8k16.row.col.f32.f16.f16.f32 "
        "{%0,%1,%2,%3}, {%4,%5,%6,%7}, {%8,%9}, {%0,%1,%2,%3};"
        : "+f"(c[0]), "+f"(c[1]), "+f"(c[2]), "+f"(c[3])
        : "r"(a[0]), "r"(a[1]), "r"(a[2]), "r"(a[3]), "r"(b[0]), "r"(b[1]));
}

// ----------------------------------------------------------------------------
// LayerNorm: fp32 in, fp16 out
// ----------------------------------------------------------------------------
__inline__ __device__ float warp_sum(float v) {
    #pragma unroll
    for (int o = 16; o > 0; o >>= 1) v += __shfl_xor_sync(0xffffffffu, v, o);
    return v;
}
__global__ void ln_kernel(const float* __restrict__ x,
                          const float* __restrict__ scale,
                          const float* __restrict__ shift,
                          __half* __restrict__ out)
{
    __shared__ float ssum[8], ssq[8];
    int row = blockIdx.x;
    int t = threadIdx.x;
    const float4* xr = (const float4*)(x + (size_t)row * EMB);
    float4 v = xr[t];
    float s  = v.x + v.y + v.z + v.w;
    float sq = v.x * v.x + v.y * v.y + v.z * v.z + v.w * v.w;
    float ws  = warp_sum(s);
    float wsq = warp_sum(sq);
    int lane = t & 31, wid = t >> 5;
    if (lane == 0) { ssum[wid] = ws; ssq[wid] = wsq; }
    __syncthreads();
    float tot = 0.f, totsq = 0.f;
    #pragma unroll
    for (int i = 0; i < 8; i++) { tot += ssum[i]; totsq += ssq[i]; }
    float mean = tot * (1.0f / EMB);
    float var  = totsq * (1.0f / EMB) - mean * mean;
    float inv  = rsqrtf(var + 1e-5f);
    float4 sc = ((const float4*)scale)[t];
    float4 sh = ((const float4*)shift)[t];
    __half* op = out + (size_t)row * EMB + t * 4;
    *(half2*)op       = __floats2half2_rn(sc.x * (v.x - mean) * inv + sh.x,
                                          sc.y * (v.y - mean) * inv + sh.y);
    *(half2*)(op + 2) = __floats2half2_rn(sc.z * (v.z - mean) * inv + sh.z,
                                          sc.w * (v.w - mean) * inv + sh.w);
}

// ----------------------------------------------------------------------------
// Weight prep: fp32 -> fp16 (and QKV pack)
// ----------------------------------------------------------------------------
__global__ void tohalf(const float* __restrict__ in, __half* __restrict__ out, int n)
{
    int i = (blockIdx.x * blockDim.x + threadIdx.x) * 8;
    if (i < n) {
        float4 a = *(const float4*)(in + i);
        float4 b = *(const float4*)(in + i + 4);
        half2 h0 = __floats2half2_rn(a.x, a.y);
        half2 h1 = __floats2half2_rn(a.z, a.w);
        half2 h2 = __floats2half2_rn(b.x, b.y);
        half2 h3 = __floats2half2_rn(b.z, b.w);
        uint4 u;
        u.x = *(uint32_t*)&h0; u.y = *(uint32_t*)&h1;
        u.z = *(uint32_t*)&h2; u.w = *(uint32_t*)&h3;
        *(uint4*)(out + i) = u;
    }
}
__global__ void pack_qkv_h(const float* __restrict__ Wq, const float* __restrict__ Wk,
                           const float* __restrict__ Wv, __half* __restrict__ out)
{
    int i = (blockIdx.x * blockDim.x + threadIdx.x) * 4;
    int k = i >> 10;
    int n = i & 1023;
    float4 a = *(const float4*)(Wq + i);
    float4 b = *(const float4*)(Wk + i);
    float4 c = *(const float4*)(Wv + i);
    __half* o = out + (size_t)k * QKVN + n;
    *(half2*)(o)               = __floats2half2_rn(a.x, a.y);
    *(half2*)(o + 2)           = __floats2half2_rn(a.z, a.w);
    *(half2*)(o + EMB)         = __floats2half2_rn(b.x, b.y);
    *(half2*)(o + EMB + 2)     = __floats2half2_rn(b.z, b.w);
    *(half2*)(o + 2 * EMB)     = __floats2half2_rn(c.x, c.y);
    *(half2*)(o + 2 * EMB + 2) = __floats2half2_rn(c.z, c.w);
}

// ----------------------------------------------------------------------------
// fp16 mma.sync GEMM, 4-stage cp.async pipeline, one __syncthreads per k-tile.
// CTA 128x128, BK=32, 256 threads (8 warps, 4Mx2N), warp tile 32x64.
// flags: 1 = gelu, 2 = fp16 output
// ----------------------------------------------------------------------------
#define BK 32
#define AP 40
#define BPH 136
#define NSTG 4
#define A_STGH (128 * AP)
#define B_STGH (BK * BPH)
#define STG_H (A_STGH + B_STGH)
#define GEMM_SMEM (NSTG * STG_H * 2)

__global__ void __launch_bounds__(256, 1)
gemm_mma(const __half* __restrict__ A, const __half* __restrict__ B,
         const float* __restrict__ bias, const float* __restrict__ res,
         void* __restrict__ Cout, int N, int K, int flags)
{
    extern __shared__ __half smh[];

    const int tid  = threadIdx.x;
    const int lane = tid & 31;
    const int warp = tid >> 5;
    const int wm   = warp & 3;
    const int wn   = warp >> 2;
    const int brow = blockIdx.y * 128;
    const int bcol = blockIdx.x * 128;
    const int g = lane >> 2, t = lane & 3;

    float acc[2][8][4];
    #pragma unroll
    for (int mt = 0; mt < 2; mt++)
        #pragma unroll
        for (int nt = 0; nt < 8; nt++)
            #pragma unroll
            for (int e = 0; e < 4; e++) acc[mt][nt][e] = 0.f;

    const int nk = K / BK;

    // per-thread load coords (stage-invariant)
    const int a_row0 = tid >> 2,        a_c0 = (tid & 3) * 8;
    const int a_row1 = (tid + 256) >> 2, a_c1 = ((tid + 256) & 3) * 8;
    const int b_row0 = tid >> 4,        b_c0 = (tid & 15) * 8;
    const int b_row1 = (tid + 256) >> 4, b_c1 = ((tid + 256) & 15) * 8;

    auto load_stage = [&](int st, int k0) {
        __half* as = smh + st * STG_H;
        __half* bs = as + A_STGH;
        cp16(as + a_row0 * AP + a_c0, A + (size_t)(brow + a_row0) * K + k0 + a_c0);
        cp16(as + a_row1 * AP + a_c1, A + (size_t)(brow + a_row1) * K + k0 + a_c1);
        cp16(bs + b_row0 * BPH + b_c0, B + (size_t)(k0 + b_row0) * N + bcol + b_c0);
        cp16(bs + b_row1 * BPH + b_c1, B + (size_t)(k0 + b_row1) * N + bcol + b_c1);
        asm volatile("cp.async.commit_group;" ::: "memory");
    };

    // prefetch NSTG-1 stages
    #pragma unroll
    for (int s = 0; s < NSTG - 1; s++) load_stage(s, s * BK);

    const int lr = lane & 15;
    const int lc = (lane >> 4) * 8;
    const int br = lane & 7;
    const int bseg = lane >> 3;

    for (int kt = 0; kt < nk; kt++) {
        asm volatile("cp.async.wait_group %0;" :: "n"(NSTG - 2) : "memory");
        __syncthreads();

        // issue next stage (or empty commit to keep group accounting exact)
        int nxt = kt + NSTG - 1;
        if (nxt < nk) load_stage(nxt & (NSTG - 1), nxt * BK);
        else asm volatile("cp.async.commit_group;" ::: "memory");

        const __half* as = smh + (kt & (NSTG - 1)) * STG_H + (wm * 32) * AP;
        const __half* bs = smh + (kt & (NSTG - 1)) * STG_H + A_STGH + wn * 64;

        #pragma unroll
        for (int ks = 0; ks < 2; ks++) {
            const int k = ks * 16;
            uint32_t af[2][4];
            #pragma unroll
            for (int mt = 0; mt < 2; mt++)
                ldsm_x4(af[mt], smem_u32(as + (mt * 16 + lr) * AP + k + lc));
            #pragma unroll
            for (int nb = 0; nb < 4; nb++) {
                uint32_t bf[4];
                ldsm_x4t(bf, smem_u32(bs + (k + (bseg & 1) * 8 + br) * BPH
                                         + nb * 16 + (bseg >> 1) * 8));
                #pragma unroll
                for (int mt = 0; mt < 2; mt++) {
                    mma16(acc[mt][nb * 2],     af[mt], bf);
                    mma16(acc[mt][nb * 2 + 1], af[mt], bf + 2);
                }
            }
        }
    }

    // ---------------- epilogue ----------------
    #pragma unroll
    for (int mt = 0; mt < 2; mt++) {
        int r0 = brow + wm * 32 + mt * 16 + g;
        #pragma unroll
        for (int nt = 0; nt < 8; nt++) {
            int col = bcol + wn * 64 + nt * 8 + t * 2;
            float v0 = acc[mt][nt][0], v1 = acc[mt][nt][1];
            float v2 = acc[mt][nt][2], v3 = acc[mt][nt][3];
            if (bias) {
                float b0 = __ldg(bias + col), b1 = __ldg(bias + col + 1);
                v0 += b0; v1 += b1; v2 += b0; v3 += b1;
            }
            if (flags & 1) {
                v0 = gelu_tanh(v0); v1 = gelu_tanh(v1);
                v2 = gelu_tanh(v2); v3 = gelu_tanh(v3);
            }
            size_t i0 = (size_t)r0 * N + col;
            size_t i1 = (size_t)(r0 + 8) * N + col;
            if (res) {
                float2 r0v = *(const float2*)(res + i0);
                float2 r1v = *(const float2*)(res + i1);
                v0 += r0v.x; v1 += r0v.y; v2 += r1v.x; v3 += r1v.y;
            }
            if (flags & 2) {
                *(half2*)((__half*)Cout + i0) = __floats2half2_rn(v0, v1);
                *(half2*)((__half*)Cout + i1) = __floats2half2_rn(v2, v3);
            } else {
                *(float2*)((float*)Cout + i0) = make_float2(v0, v1);
                *(float2*)((float*)Cout + i1) = make_float2(v2, v3);
            }
        }
    }
}

// ----------------------------------------------------------------------------
// fp16 tensor-core causal flash attention (unchanged from R6 pass)
// ----------------------------------------------------------------------------
#define HP 72
#define TILE_H (64 * HP)
#define ATTN_SMEM (5 * TILE_H * 2)

__global__ void __launch_bounds__(128, 2)
attn_mma(const __half* __restrict__ qkv, __half* __restrict__ ctx)
{
    extern __shared__ __half smh[];
    __half* Qsh = smh;
    __half* Ksh = smh + TILE_H;
    __half* Vsh = Ksh + 2 * TILE_H;

    const int bh = blockIdx.x;
    const int qb = blockIdx.y;
    const int b = bh >> 4, h = bh & 15;
    const int tid = threadIdx.x, lane = tid & 31, w = tid >> 5;
    const int g = lane >> 2, t = lane & 3;
    const int lr = lane & 15, lc = (lane >> 4) * 8;
    const int br = lane & 7, bseg = lane >> 3;

    const __half* qbase = qkv + ((size_t)(b * SEQ + qb * 64)) * QKVN + h * HDIM;
    for (int i = tid; i < 64 * 8; i += 128) {
        int r = i >> 3, c = i & 7;
        *(uint4*)(Qsh + r * HP + c * 8) = *(const uint4*)(qbase + (size_t)r * QKVN + c * 8);
    }
    __syncthreads();

    uint32_t qf[4][4];
    #pragma unroll
    for (int kc = 0; kc < 4; kc++)
        ldsm_x4(qf[kc], smem_u32(Qsh + (w * 16 + lr) * HP + kc * 16 + lc));
    __syncthreads();

    float oacc[8][4];
    #pragma unroll
    for (int nt = 0; nt < 8; nt++)
        #pragma unroll
        for (int e = 0; e < 4; e++) oacc[nt][e] = 0.f;

    float m_lo = -INFINITY, m_hi = -INFINITY, l_lo = 0.f, l_hi = 0.f;
    const float scale = 0.125f;

    auto load_kv = [&](int kt, int st) {
        const __half* kb = qkv + ((size_t)(b * SEQ + kt * 64)) * QKVN + h * HDIM + EMB;
        const __half* vb = kb + EMB;
        __half* ks = Ksh + st * TILE_H;
        __half* vs = Vsh + st * TILE_H;
        for (int i = tid; i < 64 * 8; i += 128) {
            int r = i >> 3, c = i & 7;
            cp16(ks + r * HP + c * 8, kb + (size_t)r * QKVN + c * 8);
            cp16(vs + r * HP + c * 8, vb + (size_t)r * QKVN + c * 8);
        }
        asm volatile("cp.async.commit_group;" ::: "memory");
    };

    load_kv(0, 0);

    __half* Pw = Qsh + (w * 16) * HP;

    for (int kt = 0; kt <= qb; kt++) {
        int st = kt & 1;
        if (kt < qb) {
            load_kv(kt + 1, st ^ 1);
            asm volatile("cp.async.wait_group 1;" ::: "memory");
        } else {
            asm volatile("cp.async.wait_group 0;" ::: "memory");
        }
        __syncthreads();

        const __half* ks = Ksh + st * TILE_H;
        const __half* vs = Vsh + st * TILE_H;

        float sacc[8][4];
        #pragma unroll
        for (int nt = 0; nt < 8; nt++)
            #pragma unroll
            for (int e = 0; e < 4; e++) sacc[nt][e] = 0.f;
        #pragma unroll
        for (int kc = 0; kc < 4; kc++) {
            #pragma unroll
            for (int nb = 0; nb < 4; nb++) {
                uint32_t kf[4];
                ldsm_x4(kf, smem_u32(ks + (nb * 16 + (bseg >> 1) * 8 + br) * HP
                                        + kc * 16 + (bseg & 1) * 8));
                mma16(sacc[nb * 2],     qf[kc], kf);
                mma16(sacc[nb * 2 + 1], qf[kc], kf + 2);
            }
        }

        float tl = -INFINITY, th = -INFINITY;
        const int row_lo = w * 16 + g;
        const int row_hi = row_lo + 8;
        #pragma unroll
        for (int nt = 0; nt < 8; nt++) {
            float s0 = sacc[nt][0] * scale;
            float s1 = sacc[nt][1] * scale;
            float s2 = sacc[nt][2] * scale;
            float s3 = sacc[nt][3] * scale;
            if (kt == qb) {
                int c0 = nt * 8 + t * 2, c1 = c0 + 1;
                if (c0 > row_lo) s0 = -INFINITY;
                if (c1 > row_lo) s1 = -INFINITY;
                if (c0 > row_hi) s2 = -INFINITY;
                if (c1 > row_hi) s3 = -INFINITY;
            }
            sacc[nt][0] = s0; sacc[nt][1] = s1; sacc[nt][2] = s2; sacc[nt][3] = s3;
            tl = fmaxf(tl, fmaxf(s0, s1));
            th = fmaxf(th, fmaxf(s2, s3));
        }
        tl = fmaxf(tl, __shfl_xor_sync(0xffffffffu, tl, 1));
        tl = fmaxf(tl, __shfl_xor_sync(0xffffffffu, tl, 2));
        th = fmaxf(th, __shfl_xor_sync(0xffffffffu, th, 1));
        th = fmaxf(th, __shfl_xor_sync(0xffffffffu, th, 2));

        float mn_lo = fmaxf(m_lo, tl);
        float mn_hi = fmaxf(m_hi, th);
        float c_lo = __expf(m_lo - mn_lo);
        float c_hi = __expf(m_hi - mn_hi);

        float sl = 0.f, sh2 = 0.f;
        #pragma unroll
        for (int nt = 0; nt < 8; nt++) {
            float p0 = __expf(sacc[nt][0] - mn_lo);
            float p1 = __expf(sacc[nt][1] - mn_lo);
            float p2 = __expf(sacc[nt][2] - mn_hi);
            float p3 = __expf(sacc[nt][3] - mn_hi);
            sl += p0 + p1; sh2 += p2 + p3;
            int c = nt * 8 + t * 2;
            *(half2*)&Pw[g * HP + c]       = __floats2half2_rn(p0, p1);
            *(half2*)&Pw[(g + 8) * HP + c] = __floats2half2_rn(p2, p3);
        }
        sl  += __shfl_xor_sync(0xffffffffu, sl, 1);
        sl  += __shfl_xor_sync(0xffffffffu, sl, 2);
        sh2 += __shfl_xor_sync(0xffffffffu, sh2, 1);
        sh2 += __shfl_xor_sync(0xffffffffu, sh2, 2);
        l_lo = l_lo * c_lo + sl;
        l_hi = l_hi * c_hi + sh2;
        m_lo = mn_lo; m_hi = mn_hi;

        #pragma unroll
        for (int nt = 0; nt < 8; nt++) {
            oacc[nt][0] *= c_lo; oacc[nt][1] *= c_lo;
            oacc[nt][2] *= c_hi; oacc[nt][3] *= c_hi;
        }
        __syncwarp();

        #pragma unroll
        for (int kc = 0; kc < 4; kc++) {
            uint32_t pf[4];
            ldsm_x4(pf, smem_u32(Pw + lr * HP + kc * 16 + lc));
            #pragma unroll
            for (int nb = 0; nb < 4; nb++) {
                uint32_t vf[4];
                ldsm_x4t(vf, smem_u32(vs + (kc * 16 + (bseg & 1) * 8 + br) * HP
                                         + nb * 16 + (bseg >> 1) * 8));
                mma16(oacc[nb * 2],     pf, vf);
                mma16(oacc[nb * 2 + 1], pf, vf + 2);
            }
        }
        __syncthreads();
    }

    float inv_lo = 1.f / l_lo, inv_hi = 1.f / l_hi;
    __half* ob = ctx + ((size_t)(b * SEQ + qb * 64 + w * 16)) * EMB + h * HDIM;
    #pragma unroll
    for (int nt = 0; nt < 8; nt++) {
        int c = nt * 8 + t * 2;
        *(half2*)(ob + (size_t)g * EMB + c) =
            __floats2half2_rn(oacc[nt][0] * inv_lo, oacc[nt][1] * inv_lo);
        *(half2*)(ob + (size_t)(g + 8) * EMB + c) =
            __floats2half2_rn(oacc[nt][2] * inv_hi, oacc[nt][3] * inv_hi);
    }
}

// ----------------------------------------------------------------------------
// Launch
// ----------------------------------------------------------------------------
extern "C" void kernel_launch(void* const* d_in, const int* in_sizes, int n_in,
                              void* d_out, int out_size)
{
    const float* x    = (const float*)d_in[0];
    const float* Wq   = (const float*)d_in[1];
    const float* Wk   = (const float*)d_in[2];
    const float* Wv   = (const float*)d_in[3];
    const float* Wo   = (const float*)d_in[4];
    const float* bo   = (const float*)d_in[5];
    const float* W1   = (const float*)d_in[6];
    const float* b1   = (const float*)d_in[7];
    const float* W2   = (const float*)d_in[8];
    const float* b2   = (const float*)d_in[9];
    const float* ln1s = (const float*)d_in[10];
    const float* ln1b = (const float*)d_in[11];
    const float* ln2s = (const float*)d_in[12];
    const float* ln2b = (const float*)d_in[13];
    float* out = (float*)d_out;

    __half *h_p, *qkv_p, *ctx_p, *ff_p, *wqkv_p, *wo_p, *w1_p, *w2_p;
    float *x1_p;
    cudaGetSymbolAddress((void**)&h_p,    g_h);
    cudaGetSymbolAddress((void**)&qkv_p,  g_qkv);
    cudaGetSymbolAddress((void**)&ctx_p,  g_ctx);
    cudaGetSymbolAddress((void**)&x1_p,   g_x1);
    cudaGetSymbolAddress((void**)&ff_p,   g_ff);
    cudaGetSymbolAddress((void**)&wqkv_p, g_wqkv);
    cudaGetSymbolAddress((void**)&wo_p,   g_wo);
    cudaGetSymbolAddress((void**)&w1_p,   g_w1);
    cudaGetSymbolAddress((void**)&w2_p,   g_w2);

    cudaFuncSetAttribute(gemm_mma, cudaFuncAttributeMaxDynamicSharedMemorySize, GEMM_SMEM);
    cudaFuncSetAttribute(attn_mma, cudaFuncAttributeMaxDynamicSharedMemorySize, ATTN_SMEM);

    // weight prep (fp32 -> fp16)
    pack_qkv_h<<<(EMB * EMB / 4 + 255) / 256, 256>>>(Wq, Wk, Wv, wqkv_p);
    tohalf<<<(EMB * EMB / 8 + 255) / 256, 256>>>(Wo, wo_p, EMB * EMB);
    tohalf<<<(EMB * FFDIM / 8 + 255) / 256, 256>>>(W1, w1_p, EMB * FFDIM);
    tohalf<<<(EMB * FFDIM / 8 + 255) / 256, 256>>>(W2, w2_p, FFDIM * EMB);

    // 1) LN1 -> fp16
    ln_kernel<<<MROWS, 256>>>(x, ln1s, ln1b, h_p);

    dim3 gqkv(QKVN / 128, MROWS / 128);
    dim3 g1024(EMB / 128, MROWS / 128);
    dim3 g4096(FFDIM / 128, MROWS / 128);

    // 2) fused QKV projection -> fp16
    gemm_mma<<<gqkv, 256, GEMM_SMEM>>>(h_p, wqkv_p, nullptr, nullptr, qkv_p, QKVN, EMB, 2);

    // 3) causal attention (fp16 tensor cores) -> fp16 ctx
    dim3 attn_grid(BATCH * HEADS, SEQ / 64);
    attn_mma<<<attn_grid, 128, ATTN_SMEM>>>(qkv_p, ctx_p);

    // 4) x1 = x + ctx @ Wo + bo  (fp32 out)
    gemm_mma<<<g1024, 256, GEMM_SMEM>>>(ctx_p, wo_p, bo, x, x1_p, EMB, EMB, 0);

    // 5) LN2 -> fp16
    ln_kernel<<<MROWS, 256>>>(x1_p, ln2s, ln2b, h_p);

    // 6) ff = gelu(h @ W1 + b1) -> fp16
    gemm_mma<<<g4096, 256, GEMM_SMEM>>>(h_p, w1_p, b1, nullptr, ff_p, FFDIM, EMB, 3);

    // 7) out = x1 + ff @ W2 + b2  (fp32 out)
    gemm_mma<<<g1024, 256, GEMM_SMEM>>>(ff_p, w2_p, b2, x1_p, out, EMB, FFDIM, 0);
}

// round 8
// speedup vs baseline: 6.5389x; 1.1788x over previous
#include <cuda_runtime.h>
#include <cuda_fp16.h>
#include <math.h>
#include <stdint.h>

#define BATCH 2
#define SEQ   2048
#define EMB   1024
#define HEADS 16
#define HDIM  64
#define FFDIM 4096
#define MROWS (BATCH * SEQ)   // 4096
#define QKVN  (3 * EMB)       // 3072

// ----------------------------------------------------------------------------
// Scratch (device globals — no runtime allocation allowed)
// ----------------------------------------------------------------------------
__device__ __half g_h   [MROWS * EMB];
__device__ __half g_qkv [MROWS * QKVN];
__device__ __half g_ctx [MROWS * EMB];
__device__ float  g_x1  [MROWS * EMB];
__device__ __half g_ff  [MROWS * FFDIM];
__device__ __half g_wqkv[EMB * QKVN];
__device__ __half g_wo  [EMB * EMB];
__device__ __half g_w1  [EMB * FFDIM];
__device__ __half g_w2  [FFDIM * EMB];

// ----------------------------------------------------------------------------
// Helpers
// ----------------------------------------------------------------------------
__device__ __forceinline__ uint32_t smem_u32(const void* p) {
    uint32_t a;
    asm("{ .reg .u64 t; cvta.to.shared.u64 t, %1; cvt.u32.u64 %0, t; }" : "=r"(a) : "l"(p));
    return a;
}
__device__ __forceinline__ void cp16(void* dst, const void* src) {
    asm volatile("cp.async.cg.shared.global [%0], [%1], 16;"
                 :: "r"(smem_u32(dst)), "l"(src) : "memory");
}
__device__ __forceinline__ float gelu_tanh(float x) {
    const float c = 0.7978845608028654f;
    return 0.5f * x * (1.0f + tanhf(c * (x + 0.044715f * x * x * x)));
}
__device__ __forceinline__ void ldsm_x4(uint32_t* r, uint32_t addr) {
    asm volatile("ldmatrix.sync.aligned.m8n8.x4.shared.b16 {%0,%1,%2,%3}, [%4];"
                 : "=r"(r[0]), "=r"(r[1]), "=r"(r[2]), "=r"(r[3]) : "r"(addr));
}
__device__ __forceinline__ void ldsm_x4t(uint32_t* r, uint32_t addr) {
    asm volatile("ldmatrix.sync.aligned.m8n8.x4.trans.shared.b16 {%0,%1,%2,%3}, [%4];"
                 : "=r"(r[0]), "=r"(r[1]), "=r"(r[2]), "=r"(r[3]) : "r"(addr));
}
__device__ __forceinline__ void mma16(float* c, const uint32_t* a, const uint32_t* b) {
    asm volatile(
        "mma.sync.aligned.m16n8k16.row.col.f32.f16.f16.f32 "
        "{%0,%1,%2,%3}, {%4,%5,%6,%7}, {%8,%9}, {%0,%1,%2,%3};"
        : "+f"(c[0]), "+f"(c[1]), "+f"(c[2]), "+f"(c[3])
        : "r"(a[0]), "r"(a[1]), "r"(a[2]), "r"(a[3]), "r"(b[0]), "r"(b[1]));
}

// ----------------------------------------------------------------------------
// LayerNorm: fp32 in, fp16 out
// ----------------------------------------------------------------------------
__inline__ __device__ float warp_sum(float v) {
    #pragma unroll
    for (int o = 16; o > 0; o >>= 1) v += __shfl_xor_sync(0xffffffffu, v, o);
    return v;
}
__global__ void ln_kernel(const float* __restrict__ x,
                          const float* __restrict__ scale,
                          const float* __restrict__ shift,
                          __half* __restrict__ out)
{
    __shared__ float ssum[8], ssq[8];
    int row = blockIdx.x;
    int t = threadIdx.x;
    const float4* xr = (const float4*)(x + (size_t)row * EMB);
    float4 v = xr[t];
    float s  = v.x + v.y + v.z + v.w;
    float sq = v.x * v.x + v.y * v.y + v.z * v.z + v.w * v.w;
    float ws  = warp_sum(s);
    float wsq = warp_sum(sq);
    int lane = t & 31, wid = t >> 5;
    if (lane == 0) { ssum[wid] = ws; ssq[wid] = wsq; }
    __syncthreads();
    float tot = 0.f, totsq = 0.f;
    #pragma unroll
    for (int i = 0; i < 8; i++) { tot += ssum[i]; totsq += ssq[i]; }
    float mean = tot * (1.0f / EMB);
    float var  = totsq * (1.0f / EMB) - mean * mean;
    float inv  = rsqrtf(var + 1e-5f);
    float4 sc = ((const float4*)scale)[t];
    float4 sh = ((const float4*)shift)[t];
    __half* op = out + (size_t)row * EMB + t * 4;
    *(half2*)op       = __floats2half2_rn(sc.x * (v.x - mean) * inv + sh.x,
                                          sc.y * (v.y - mean) * inv + sh.y);
    *(half2*)(op + 2) = __floats2half2_rn(sc.z * (v.z - mean) * inv + sh.z,
                                          sc.w * (v.w - mean) * inv + sh.w);
}

// ----------------------------------------------------------------------------
// Weight prep: fp32 -> fp16 (and QKV pack)
// ----------------------------------------------------------------------------
__global__ void tohalf(const float* __restrict__ in, __half* __restrict__ out, int n)
{
    int i = (blockIdx.x * blockDim.x + threadIdx.x) * 8;
    if (i < n) {
        float4 a = *(const float4*)(in + i);
        float4 b = *(const float4*)(in + i + 4);
        half2 h0 = __floats2half2_rn(a.x, a.y);
        half2 h1 = __floats2half2_rn(a.z, a.w);
        half2 h2 = __floats2half2_rn(b.x, b.y);
        half2 h3 = __floats2half2_rn(b.z, b.w);
        uint4 u;
        u.x = *(uint32_t*)&h0; u.y = *(uint32_t*)&h1;
        u.z = *(uint32_t*)&h2; u.w = *(uint32_t*)&h3;
        *(uint4*)(out + i) = u;
    }
}
__global__ void pack_qkv_h(const float* __restrict__ Wq, const float* __restrict__ Wk,
                           const float* __restrict__ Wv, __half* __restrict__ out)
{
    int i = (blockIdx.x * blockDim.x + threadIdx.x) * 4;
    int k = i >> 10;
    int n = i & 1023;
    float4 a = *(const float4*)(Wq + i);
    float4 b = *(const float4*)(Wk + i);
    float4 c = *(const float4*)(Wv + i);
    __half* o = out + (size_t)k * QKVN + n;
    *(half2*)(o)               = __floats2half2_rn(a.x, a.y);
    *(half2*)(o + 2)           = __floats2half2_rn(a.z, a.w);
    *(half2*)(o + EMB)         = __floats2half2_rn(b.x, b.y);
    *(half2*)(o + EMB + 2)     = __floats2half2_rn(b.z, b.w);
    *(half2*)(o + 2 * EMB)     = __floats2half2_rn(c.x, c.y);
    *(half2*)(o + 2 * EMB + 2) = __floats2half2_rn(c.z, c.w);
}

// ----------------------------------------------------------------------------
// fp16 mma.sync GEMM, 4-stage cp.async pipeline.
// CTA 256x128, BK=32, 512 threads (16 warps, 4Mx4N), warp tile 64x32.
// flags: 1 = gelu, 2 = fp16 output
// ----------------------------------------------------------------------------
#define BK 32
#define BM 256
#define AP 40
#define BPH 136
#define NSTG 4
#define A_STGH (BM * AP)
#define B_STGH (BK * BPH)
#define STG_H (A_STGH + B_STGH)
#define GEMM_SMEM (NSTG * STG_H * 2)

__global__ void __launch_bounds__(512, 1)
gemm_mma(const __half* __restrict__ A, const __half* __restrict__ B,
         const float* __restrict__ bias, const float* __restrict__ res,
         void* __restrict__ Cout, int N, int K, int flags)
{
    extern __shared__ __half smh[];

    const int tid  = threadIdx.x;
    const int lane = tid & 31;
    const int warp = tid >> 5;       // 0..15
    const int wm   = warp & 3;       // M quadrant (64 rows)
    const int wn   = warp >> 2;      // N quadrant (32 cols)
    const int brow = blockIdx.y * BM;
    const int bcol = blockIdx.x * 128;
    const int g = lane >> 2, t = lane & 3;

    float acc[4][4][4];
    #pragma unroll
    for (int mt = 0; mt < 4; mt++)
        #pragma unroll
        for (int nt = 0; nt < 4; nt++)
            #pragma unroll
            for (int e = 0; e < 4; e++) acc[mt][nt][e] = 0.f;

    const int nk = K / BK;

    // per-thread load coords (stage-invariant)
    const int a_row0 = tid >> 2,         a_c0 = (tid & 3) * 8;
    const int a_row1 = (tid + 512) >> 2, a_c1 = a_c0;
    const int b_row0 = tid >> 4,         b_c0 = (tid & 15) * 8;

    auto load_stage = [&](int st, int k0) {
        __half* as = smh + st * STG_H;
        __half* bs = as + A_STGH;
        cp16(as + a_row0 * AP + a_c0, A + (size_t)(brow + a_row0) * K + k0 + a_c0);
        cp16(as + a_row1 * AP + a_c1, A + (size_t)(brow + a_row1) * K + k0 + a_c1);
        cp16(bs + b_row0 * BPH + b_c0, B + (size_t)(k0 + b_row0) * N + bcol + b_c0);
        asm volatile("cp.async.commit_group;" ::: "memory");
    };

    #pragma unroll
    for (int s = 0; s < NSTG - 1; s++) load_stage(s, s * BK);

    const int lr = lane & 15;
    const int lc = (lane >> 4) * 8;
    const int br = lane & 7;
    const int bseg = lane >> 3;

    for (int kt = 0; kt < nk; kt++) {
        asm volatile("cp.async.wait_group %0;" :: "n"(NSTG - 2) : "memory");
        __syncthreads();

        int nxt = kt + NSTG - 1;
        if (nxt < nk) load_stage(nxt & (NSTG - 1), nxt * BK);
        else asm volatile("cp.async.commit_group;" ::: "memory");

        const __half* as = smh + (kt & (NSTG - 1)) * STG_H + (wm * 64) * AP;
        const __half* bs = smh + (kt & (NSTG - 1)) * STG_H + A_STGH + wn * 32;

        #pragma unroll
        for (int ks = 0; ks < 2; ks++) {
            const int k = ks * 16;
            uint32_t af[4][4];
            #pragma unroll
            for (int mt = 0; mt < 4; mt++)
                ldsm_x4(af[mt], smem_u32(as + (mt * 16 + lr) * AP + k + lc));
            #pragma unroll
            for (int nbh = 0; nbh < 2; nbh++) {
                uint32_t bf[4];
                ldsm_x4t(bf, smem_u32(bs + (k + (bseg & 1) * 8 + br) * BPH
                                         + nbh * 16 + (bseg >> 1) * 8));
                #pragma unroll
                for (int mt = 0; mt < 4; mt++) {
                    mma16(acc[mt][nbh * 2],     af[mt], bf);
                    mma16(acc[mt][nbh * 2 + 1], af[mt], bf + 2);
                }
            }
        }
    }

    // ---------------- epilogue ----------------
    #pragma unroll
    for (int mt = 0; mt < 4; mt++) {
        int r0 = brow + wm * 64 + mt * 16 + g;
        #pragma unroll
        for (int nt = 0; nt < 4; nt++) {
            int col = bcol + wn * 32 + nt * 8 + t * 2;
            float v0 = acc[mt][nt][0], v1 = acc[mt][nt][1];
            float v2 = acc[mt][nt][2], v3 = acc[mt][nt][3];
            if (bias) {
                float b0 = __ldg(bias + col), b1 = __ldg(bias + col + 1);
                v0 += b0; v1 += b1; v2 += b0; v3 += b1;
            }
            if (flags & 1) {
                v0 = gelu_tanh(v0); v1 = gelu_tanh(v1);
                v2 = gelu_tanh(v2); v3 = gelu_tanh(v3);
            }
            size_t i0 = (size_t)r0 * N + col;
            size_t i1 = (size_t)(r0 + 8) * N + col;
            if (res) {
                float2 r0v = *(const float2*)(res + i0);
                float2 r1v = *(const float2*)(res + i1);
                v0 += r0v.x; v1 += r0v.y; v2 += r1v.x; v3 += r1v.y;
            }
            if (flags & 2) {
                *(half2*)((__half*)Cout + i0) = __floats2half2_rn(v0, v1);
                *(half2*)((__half*)Cout + i1) = __floats2half2_rn(v2, v3);
            } else {
                *(float2*)((float*)Cout + i0) = make_float2(v0, v1);
                *(float2*)((float*)Cout + i1) = make_float2(v2, v3);
            }
        }
    }
}

// ----------------------------------------------------------------------------
// fp16 tensor-core causal flash attention
// ----------------------------------------------------------------------------
#define HP 72
#define TILE_H (64 * HP)
#define ATTN_SMEM (5 * TILE_H * 2)

__global__ void __launch_bounds__(128)
attn_mma(const __half* __restrict__ qkv, __half* __restrict__ ctx)
{
    extern __shared__ __half smh[];
    __half* Qsh = smh;
    __half* Ksh = smh + TILE_H;
    __half* Vsh = Ksh + 2 * TILE_H;

    const int bh = blockIdx.x;
    const int qb = gridDim.y - 1 - blockIdx.y;   // heavy tiles first
    const int b = bh >> 4, h = bh & 15;
    const int tid = threadIdx.x, lane = tid & 31, w = tid >> 5;
    const int g = lane >> 2, t = lane & 3;
    const int lr = lane & 15, lc = (lane >> 4) * 8;
    const int br = lane & 7, bseg = lane >> 3;

    const __half* qbase = qkv + ((size_t)(b * SEQ + qb * 64)) * QKVN + h * HDIM;
    for (int i = tid; i < 64 * 8; i += 128) {
        int r = i >> 3, c = i & 7;
        *(uint4*)(Qsh + r * HP + c * 8) = *(const uint4*)(qbase + (size_t)r * QKVN + c * 8);
    }
    __syncthreads();

    uint32_t qf[4][4];
    #pragma unroll
    for (int kc = 0; kc < 4; kc++)
        ldsm_x4(qf[kc], smem_u32(Qsh + (w * 16 + lr) * HP + kc * 16 + lc));
    __syncthreads();

    float oacc[8][4];
    #pragma unroll
    for (int nt = 0; nt < 8; nt++)
        #pragma unroll
        for (int e = 0; e < 4; e++) oacc[nt][e] = 0.f;

    float m_lo = -INFINITY, m_hi = -INFINITY, l_lo = 0.f, l_hi = 0.f;
    const float scale = 0.125f;

    auto load_kv = [&](int kt, int st) {
        const __half* kb = qkv + ((size_t)(b * SEQ + kt * 64)) * QKVN + h * HDIM + EMB;
        const __half* vb = kb + EMB;
        __half* ks = Ksh + st * TILE_H;
        __half* vs = Vsh + st * TILE_H;
        for (int i = tid; i < 64 * 8; i += 128) {
            int r = i >> 3, c = i & 7;
            cp16(ks + r * HP + c * 8, kb + (size_t)r * QKVN + c * 8);
            cp16(vs + r * HP + c * 8, vb + (size_t)r * QKVN + c * 8);
        }
        asm volatile("cp.async.commit_group;" ::: "memory");
    };

    load_kv(0, 0);

    __half* Pw = Qsh + (w * 16) * HP;

    for (int kt = 0; kt <= qb; kt++) {
        int st = kt & 1;
        if (kt < qb) {
            load_kv(kt + 1, st ^ 1);
            asm volatile("cp.async.wait_group 1;" ::: "memory");
        } else {
            asm volatile("cp.async.wait_group 0;" ::: "memory");
        }
        __syncthreads();

        const __half* ks = Ksh + st * TILE_H;
        const __half* vs = Vsh + st * TILE_H;

        float sacc[8][4];
        #pragma unroll
        for (int nt = 0; nt < 8; nt++)
            #pragma unroll
            for (int e = 0; e < 4; e++) sacc[nt][e] = 0.f;
        #pragma unroll
        for (int kc = 0; kc < 4; kc++) {
            #pragma unroll
            for (int nb = 0; nb < 4; nb++) {
                uint32_t kf[4];
                ldsm_x4(kf, smem_u32(ks + (nb * 16 + (bseg >> 1) * 8 + br) * HP
                                        + kc * 16 + (bseg & 1) * 8));
                mma16(sacc[nb * 2],     qf[kc], kf);
                mma16(sacc[nb * 2 + 1], qf[kc], kf + 2);
            }
        }

        float tl = -INFINITY, th = -INFINITY;
        const int row_lo = w * 16 + g;
        const int row_hi = row_lo + 8;
        #pragma unroll
        for (int nt = 0; nt < 8; nt++) {
            float s0 = sacc[nt][0] * scale;
            float s1 = sacc[nt][1] * scale;
            float s2 = sacc[nt][2] * scale;
            float s3 = sacc[nt][3] * scale;
            if (kt == qb) {
                int c0 = nt * 8 + t * 2, c1 = c0 + 1;
                if (c0 > row_lo) s0 = -INFINITY;
                if (c1 > row_lo) s1 = -INFINITY;
                if (c0 > row_hi) s2 = -INFINITY;
                if (c1 > row_hi) s3 = -INFINITY;
            }
            sacc[nt][0] = s0; sacc[nt][1] = s1; sacc[nt][2] = s2; sacc[nt][3] = s3;
            tl = fmaxf(tl, fmaxf(s0, s1));
            th = fmaxf(th, fmaxf(s2, s3));
        }
        tl = fmaxf(tl, __shfl_xor_sync(0xffffffffu, tl, 1));
        tl = fmaxf(tl, __shfl_xor_sync(0xffffffffu, tl, 2));
        th = fmaxf(th, __shfl_xor_sync(0xffffffffu, th, 1));
        th = fmaxf(th, __shfl_xor_sync(0xffffffffu, th, 2));

        float mn_lo = fmaxf(m_lo, tl);
        float mn_hi = fmaxf(m_hi, th);
        float c_lo = __expf(m_lo - mn_lo);
        float c_hi = __expf(m_hi - mn_hi);

        float sl = 0.f, sh2 = 0.f;
        #pragma unroll
        for (int nt = 0; nt < 8; nt++) {
            float p0 = __expf(sacc[nt][0] - mn_lo);
            float p1 = __expf(sacc[nt][1] - mn_lo);
            float p2 = __expf(sacc[nt][2] - mn_hi);
            float p3 = __expf(sacc[nt][3] - mn_hi);
            sl += p0 + p1; sh2 += p2 + p3;
            int c = nt * 8 + t * 2;
            *(half2*)&Pw[g * HP + c]       = __floats2half2_rn(p0, p1);
            *(half2*)&Pw[(g + 8) * HP + c] = __floats2half2_rn(p2, p3);
        }
        sl  += __shfl_xor_sync(0xffffffffu, sl, 1);
        sl  += __shfl_xor_sync(0xffffffffu, sl, 2);
        sh2 += __shfl_xor_sync(0xffffffffu, sh2, 1);
        sh2 += __shfl_xor_sync(0xffffffffu, sh2, 2);
        l_lo = l_lo * c_lo + sl;
        l_hi = l_hi * c_hi + sh2;
        m_lo = mn_lo; m_hi = mn_hi;

        #pragma unroll
        for (int nt = 0; nt < 8; nt++) {
            oacc[nt][0] *= c_lo; oacc[nt][1] *= c_lo;
            oacc[nt][2] *= c_hi; oacc[nt][3] *= c_hi;
        }
        __syncwarp();

        #pragma unroll
        for (int kc = 0; kc < 4; kc++) {
            uint32_t pf[4];
            ldsm_x4(pf, smem_u32(Pw + lr * HP + kc * 16 + lc));
            #pragma unroll
            for (int nb = 0; nb < 4; nb++) {
                uint32_t vf[4];
                ldsm_x4t(vf, smem_u32(vs + (kc * 16 + (bseg & 1) * 8 + br) * HP
                                         + nb * 16 + (bseg >> 1) * 8));
                mma16(oacc[nb * 2],     pf, vf);
                mma16(oacc[nb * 2 + 1], pf, vf + 2);
            }
        }
        __syncthreads();
    }

    float inv_lo = 1.f / l_lo, inv_hi = 1.f / l_hi;
    __half* ob = ctx + ((size_t)(b * SEQ + qb * 64 + w * 16)) * EMB + h * HDIM;
    #pragma unroll
    for (int nt = 0; nt < 8; nt++) {
        int c = nt * 8 + t * 2;
        *(half2*)(ob + (size_t)g * EMB + c) =
            __floats2half2_rn(oacc[nt][0] * inv_lo, oacc[nt][1] * inv_lo);
        *(half2*)(ob + (size_t)(g + 8) * EMB + c) =
            __floats2half2_rn(oacc[nt][2] * inv_hi, oacc[nt][3] * inv_hi);
    }
}

// ----------------------------------------------------------------------------
// Launch
// ----------------------------------------------------------------------------
extern "C" void kernel_launch(void* const* d_in, const int* in_sizes, int n_in,
                              void* d_out, int out_size)
{
    const float* x    = (const float*)d_in[0];
    const float* Wq   = (const float*)d_in[1];
    const float* Wk   = (const float*)d_in[2];
    const float* Wv   = (const float*)d_in[3];
    const float* Wo   = (const float*)d_in[4];
    const float* bo   = (const float*)d_in[5];
    const float* W1   = (const float*)d_in[6];
    const float* b1   = (const float*)d_in[7];
    const float* W2   = (const float*)d_in[8];
    const float* b2   = (const float*)d_in[9];
    const float* ln1s = (const float*)d_in[10];
    const float* ln1b = (const float*)d_in[11];
    const float* ln2s = (const float*)d_in[12];
    const float* ln2b = (const float*)d_in[13];
    float* out = (float*)d_out;

    __half *h_p, *qkv_p, *ctx_p, *ff_p, *wqkv_p, *wo_p, *w1_p, *w2_p;
    float *x1_p;
    cudaGetSymbolAddress((void**)&h_p,    g_h);
    cudaGetSymbolAddress((void**)&qkv_p,  g_qkv);
    cudaGetSymbolAddress((void**)&ctx_p,  g_ctx);
    cudaGetSymbolAddress((void**)&x1_p,   g_x1);
    cudaGetSymbolAddress((void**)&ff_p,   g_ff);
    cudaGetSymbolAddress((void**)&wqkv_p, g_wqkv);
    cudaGetSymbolAddress((void**)&wo_p,   g_wo);
    cudaGetSymbolAddress((void**)&w1_p,   g_w1);
    cudaGetSymbolAddress((void**)&w2_p,   g_w2);

    cudaFuncSetAttribute(gemm_mma, cudaFuncAttributeMaxDynamicSharedMemorySize, GEMM_SMEM);
    cudaFuncSetAttribute(attn_mma, cudaFuncAttributeMaxDynamicSharedMemorySize, ATTN_SMEM);

    // weight prep (fp32 -> fp16)
    pack_qkv_h<<<(EMB * EMB / 4 + 255) / 256, 256>>>(Wq, Wk, Wv, wqkv_p);
    tohalf<<<(EMB * EMB / 8 + 255) / 256, 256>>>(Wo, wo_p, EMB * EMB);
    tohalf<<<(EMB * FFDIM / 8 + 255) / 256, 256>>>(W1, w1_p, EMB * FFDIM);
    tohalf<<<(EMB * FFDIM / 8 + 255) / 256, 256>>>(W2, w2_p, FFDIM * EMB);

    // 1) LN1 -> fp16
    ln_kernel<<<MROWS, 256>>>(x, ln1s, ln1b, h_p);

    dim3 gqkv(QKVN / 128, MROWS / BM);     // (24, 16)
    dim3 g1024(EMB / 128, MROWS / BM);     // (8, 16) = 128 CTAs, single wave
    dim3 g4096(FFDIM / 128, MROWS / BM);   // (32, 16)

    // 2) fused QKV projection -> fp16
    gemm_mma<<<gqkv, 512, GEMM_SMEM>>>(h_p, wqkv_p, nullptr, nullptr, qkv_p, QKVN, EMB, 2);

    // 3) causal attention (fp16 tensor cores) -> fp16 ctx
    dim3 attn_grid(BATCH * HEADS, SEQ / 64);
    attn_mma<<<attn_grid, 128, ATTN_SMEM>>>(qkv_p, ctx_p);

    // 4) x1 = x + ctx @ Wo + bo  (fp32 out)
    gemm_mma<<<g1024, 512, GEMM_SMEM>>>(ctx_p, wo_p, bo, x, x1_p, EMB, EMB, 0);

    // 5) LN2 -> fp16
    ln_kernel<<<MROWS, 256>>>(x1_p, ln2s, ln2b, h_p);

    // 6) ff = gelu(h @ W1 + b1) -> fp16
    gemm_mma<<<g4096, 512, GEMM_SMEM>>>(h_p, w1_p, b1, nullptr, ff_p, FFDIM, EMB, 3);

    // 7) out = x1 + ff @ W2 + b2  (fp32 out)
    gemm_mma<<<g1024, 512, GEMM_SMEM>>>(ff_p, w2_p, b2, x1_p, out, EMB, FFDIM, 0);
}

// round 9
// speedup vs baseline: 6.9893x; 1.0689x over previous
#include <cuda_runtime.h>
#include <cuda_fp16.h>
#include <math.h>
#include <stdint.h>

#define BATCH 2
#define SEQ   2048
#define EMB   1024
#define HEADS 16
#define HDIM  64
#define FFDIM 4096
#define MROWS (BATCH * SEQ)   // 4096
#define QKVN  (3 * EMB)       // 3072

// ----------------------------------------------------------------------------
// Scratch (device globals — no runtime allocation allowed)
// ----------------------------------------------------------------------------
__device__ __half g_h   [MROWS * EMB];
__device__ __half g_qkv [MROWS * QKVN];
__device__ __half g_ctx [MROWS * EMB];
__device__ float  g_x1  [MROWS * EMB];
__device__ __half g_ff  [MROWS * FFDIM];
__device__ __half g_wqkv[EMB * QKVN];
__device__ __half g_wo  [EMB * EMB];
__device__ __half g_w1  [EMB * FFDIM];
__device__ __half g_w2  [FFDIM * EMB];

// ----------------------------------------------------------------------------
// Helpers
// ----------------------------------------------------------------------------
__device__ __forceinline__ uint32_t smem_u32(const void* p) {
    uint32_t a;
    asm("{ .reg .u64 t; cvta.to.shared.u64 t, %1; cvt.u32.u64 %0, t; }" : "=r"(a) : "l"(p));
    return a;
}
__device__ __forceinline__ void cp16(void* dst, const void* src) {
    asm volatile("cp.async.cg.shared.global [%0], [%1], 16;"
                 :: "r"(smem_u32(dst)), "l"(src) : "memory");
}
__device__ __forceinline__ float gelu_tanh(float x) {
    const float c = 0.7978845608028654f;
    return 0.5f * x * (1.0f + tanhf(c * (x + 0.044715f * x * x * x)));
}
__device__ __forceinline__ void ldsm_x4(uint32_t* r, uint32_t addr) {
    asm volatile("ldmatrix.sync.aligned.m8n8.x4.shared.b16 {%0,%1,%2,%3}, [%4];"
                 : "=r"(r[0]), "=r"(r[1]), "=r"(r[2]), "=r"(r[3]) : "r"(addr));
}
__device__ __forceinline__ void ldsm_x4t(uint32_t* r, uint32_t addr) {
    asm volatile("ldmatrix.sync.aligned.m8n8.x4.trans.shared.b16 {%0,%1,%2,%3}, [%4];"
                 : "=r"(r[0]), "=r"(r[1]), "=r"(r[2]), "=r"(r[3]) : "r"(addr));
}
__device__ __forceinline__ void mma16(float* c, const uint32_t* a, const uint32_t* b) {
    asm volatile(
        "mma.sync.aligned.m16n8k16.row.col.f32.f16.f16.f32 "
        "{%0,%1,%2,%3}, {%4,%5,%6,%7}, {%8,%9}, {%0,%1,%2,%3};"
        : "+f"(c[0]), "+f"(c[1]), "+f"(c[2]), "+f"(c[3])
        : "r"(a[0]), "r"(a[1]), "r"(a[2]), "r"(a[3]), "r"(b[0]), "r"(b[1]));
}

// ----------------------------------------------------------------------------
// LayerNorm: fp32 in, fp16 out
// ----------------------------------------------------------------------------
__inline__ __device__ float warp_sum(float v) {
    #pragma unroll
    for (int o = 16; o > 0; o >>= 1) v += __shfl_xor_sync(0xffffffffu, v, o);
    return v;
}
__global__ void ln_kernel(const float* __restrict__ x,
                          const float* __restrict__ scale,
                          const float* __restrict__ shift,
                          __half* __restrict__ out)
{
    __shared__ float ssum[8], ssq[8];
    int row = blockIdx.x;
    int t = threadIdx.x;
    const float4* xr = (const float4*)(x + (size_t)row * EMB);
    float4 v = xr[t];
    float s  = v.x + v.y + v.z + v.w;
    float sq = v.x * v.x + v.y * v.y + v.z * v.z + v.w * v.w;
    float ws  = warp_sum(s);
    float wsq = warp_sum(sq);
    int lane = t & 31, wid = t >> 5;
    if (lane == 0) { ssum[wid] = ws; ssq[wid] = wsq; }
    __syncthreads();
    float tot = 0.f, totsq = 0.f;
    #pragma unroll
    for (int i = 0; i < 8; i++) { tot += ssum[i]; totsq += ssq[i]; }
    float mean = tot * (1.0f / EMB);
    float var  = totsq * (1.0f / EMB) - mean * mean;
    float inv  = rsqrtf(var + 1e-5f);
    float4 sc = ((const float4*)scale)[t];
    float4 sh = ((const float4*)shift)[t];
    __half* op = out + (size_t)row * EMB + t * 4;
    *(half2*)op       = __floats2half2_rn(sc.x * (v.x - mean) * inv + sh.x,
                                          sc.y * (v.y - mean) * inv + sh.y);
    *(half2*)(op + 2) = __floats2half2_rn(sc.z * (v.z - mean) * inv + sh.z,
                                          sc.w * (v.w - mean) * inv + sh.w);
}

// ----------------------------------------------------------------------------
// Weight prep: fp32 -> fp16 (and QKV pack)
// ----------------------------------------------------------------------------
__global__ void tohalf(const float* __restrict__ in, __half* __restrict__ out, int n)
{
    int i = (blockIdx.x * blockDim.x + threadIdx.x) * 16;
    if (i < n) {
        float4 a = *(const float4*)(in + i);
        float4 b = *(const float4*)(in + i + 4);
        float4 c = *(const float4*)(in + i + 8);
        float4 d = *(const float4*)(in + i + 12);
        half2 h0 = __floats2half2_rn(a.x, a.y), h1 = __floats2half2_rn(a.z, a.w);
        half2 h2 = __floats2half2_rn(b.x, b.y), h3 = __floats2half2_rn(b.z, b.w);
        half2 h4 = __floats2half2_rn(c.x, c.y), h5 = __floats2half2_rn(c.z, c.w);
        half2 h6 = __floats2half2_rn(d.x, d.y), h7 = __floats2half2_rn(d.z, d.w);
        uint4 u0, u1;
        u0.x = *(uint32_t*)&h0; u0.y = *(uint32_t*)&h1;
        u0.z = *(uint32_t*)&h2; u0.w = *(uint32_t*)&h3;
        u1.x = *(uint32_t*)&h4; u1.y = *(uint32_t*)&h5;
        u1.z = *(uint32_t*)&h6; u1.w = *(uint32_t*)&h7;
        *(uint4*)(out + i)     = u0;
        *(uint4*)(out + i + 8) = u1;
    }
}
__global__ void pack_qkv_h(const float* __restrict__ Wq, const float* __restrict__ Wk,
                           const float* __restrict__ Wv, __half* __restrict__ out)
{
    int i = (blockIdx.x * blockDim.x + threadIdx.x) * 8;   // over EMB*EMB
    int k = i >> 10;
    int n = i & 1023;
    __half* o = out + (size_t)k * QKVN + n;
    const float* srcs[3] = {Wq + i, Wk + i, Wv + i};
    #pragma unroll
    for (int m = 0; m < 3; m++) {
        float4 a = *(const float4*)(srcs[m]);
        float4 b = *(const float4*)(srcs[m] + 4);
        half2 h0 = __floats2half2_rn(a.x, a.y), h1 = __floats2half2_rn(a.z, a.w);
        half2 h2 = __floats2half2_rn(b.x, b.y), h3 = __floats2half2_rn(b.z, b.w);
        uint4 u;
        u.x = *(uint32_t*)&h0; u.y = *(uint32_t*)&h1;
        u.z = *(uint32_t*)&h2; u.w = *(uint32_t*)&h3;
        *(uint4*)(o + m * EMB) = u;
    }
}

// ----------------------------------------------------------------------------
// fp16 mma.sync GEMM, BK=64, 3-stage cp.async pipeline.
// CTA 256x128, 512 threads (16 warps, 4Mx4N), warp tile 64x32.
// flags: 1 = gelu, 2 = fp16 output
// ----------------------------------------------------------------------------
#define BK 64
#define BM 256
#define AP 72
#define BPH 136
#define NSTG 3
#define A_STGH (BM * AP)
#define B_STGH (BK * BPH)
#define STG_H (A_STGH + B_STGH)
#define GEMM_SMEM (NSTG * STG_H * 2)

__global__ void __launch_bounds__(512, 1)
gemm_mma(const __half* __restrict__ A, const __half* __restrict__ B,
         const float* __restrict__ bias, const float* __restrict__ res,
         void* __restrict__ Cout, int N, int K, int flags)
{
    extern __shared__ __half smh[];

    const int tid  = threadIdx.x;
    const int lane = tid & 31;
    const int warp = tid >> 5;       // 0..15
    const int wm   = warp & 3;       // M quadrant (64 rows)
    const int wn   = warp >> 2;      // N quadrant (32 cols)
    const int brow = blockIdx.y * BM;
    const int bcol = blockIdx.x * 128;
    const int g = lane >> 2, t = lane & 3;

    float acc[4][4][4];
    #pragma unroll
    for (int mt = 0; mt < 4; mt++)
        #pragma unroll
        for (int nt = 0; nt < 4; nt++)
            #pragma unroll
            for (int e = 0; e < 4; e++) acc[mt][nt][e] = 0.f;

    const int nk = K / BK;

    auto load_stage = [&](int st, int k0) {
        __half* as = smh + st * STG_H;
        __half* bs = as + A_STGH;
        // A: 256 rows x 8 chunks (16B) = 2048 chunks, 4 per thread
        #pragma unroll
        for (int i = 0; i < 4; i++) {
            int id = tid + i * 512;
            int row = id >> 3, c = (id & 7) * 8;
            cp16(as + row * AP + c, A + (size_t)(brow + row) * K + k0 + c);
        }
        // B: 64 rows x 16 chunks = 1024 chunks, 2 per thread
        #pragma unroll
        for (int i = 0; i < 2; i++) {
            int id = tid + i * 512;
            int row = id >> 4, c = (id & 15) * 8;
            cp16(bs + row * BPH + c, B + (size_t)(k0 + row) * N + bcol + c);
        }
        asm volatile("cp.async.commit_group;" ::: "memory");
    };

    load_stage(0, 0);
    load_stage(1, BK);

    const int lr = lane & 15;
    const int lc = (lane >> 4) * 8;
    const int br = lane & 7;
    const int bseg = lane >> 3;

    int st = 0;
    for (int kt = 0; kt < nk; kt++) {
        asm volatile("cp.async.wait_group 1;" ::: "memory");
        __syncthreads();

        int nxt = kt + NSTG - 1;
        int nst = st + NSTG - 1; if (nst >= NSTG) nst -= NSTG;
        if (nxt < nk) load_stage(nst, nxt * BK);
        else asm volatile("cp.async.commit_group;" ::: "memory");

        const __half* as = smh + st * STG_H + (wm * 64) * AP;
        const __half* bs = smh + st * STG_H + A_STGH + wn * 32;

        #pragma unroll
        for (int ks = 0; ks < 4; ks++) {
            const int k = ks * 16;
            uint32_t af[4][4];
            #pragma unroll
            for (int mt = 0; mt < 4; mt++)
                ldsm_x4(af[mt], smem_u32(as + (mt * 16 + lr) * AP + k + lc));
            #pragma unroll
            for (int nbh = 0; nbh < 2; nbh++) {
                uint32_t bf[4];
                ldsm_x4t(bf, smem_u32(bs + (k + (bseg & 1) * 8 + br) * BPH
                                         + nbh * 16 + (bseg >> 1) * 8));
                #pragma unroll
                for (int mt = 0; mt < 4; mt++) {
                    mma16(acc[mt][nbh * 2],     af[mt], bf);
                    mma16(acc[mt][nbh * 2 + 1], af[mt], bf + 2);
                }
            }
        }
        if (++st == NSTG) st = 0;
    }

    // ---------------- epilogue ----------------
    #pragma unroll
    for (int mt = 0; mt < 4; mt++) {
        int r0 = brow + wm * 64 + mt * 16 + g;
        #pragma unroll
        for (int nt = 0; nt < 4; nt++) {
            int col = bcol + wn * 32 + nt * 8 + t * 2;
            float v0 = acc[mt][nt][0], v1 = acc[mt][nt][1];
            float v2 = acc[mt][nt][2], v3 = acc[mt][nt][3];
            if (bias) {
                float b0 = __ldg(bias + col), b1 = __ldg(bias + col + 1);
                v0 += b0; v1 += b1; v2 += b0; v3 += b1;
            }
            if (flags & 1) {
                v0 = gelu_tanh(v0); v1 = gelu_tanh(v1);
                v2 = gelu_tanh(v2); v3 = gelu_tanh(v3);
            }
            size_t i0 = (size_t)r0 * N + col;
            size_t i1 = (size_t)(r0 + 8) * N + col;
            if (res) {
                float2 r0v = *(const float2*)(res + i0);
                float2 r1v = *(const float2*)(res + i1);
                v0 += r0v.x; v1 += r0v.y; v2 += r1v.x; v3 += r1v.y;
            }
            if (flags & 2) {
                *(half2*)((__half*)Cout + i0) = __floats2half2_rn(v0, v1);
                *(half2*)((__half*)Cout + i1) = __floats2half2_rn(v2, v3);
            } else {
                *(float2*)((float*)Cout + i0) = make_float2(v0, v1);
                *(float2*)((float*)Cout + i1) = make_float2(v2, v3);
            }
        }
    }
}

// ----------------------------------------------------------------------------
// fp16 tensor-core causal flash attention (unchanged from R8)
// ----------------------------------------------------------------------------
#define HP 72
#define TILE_H (64 * HP)
#define ATTN_SMEM (5 * TILE_H * 2)

__global__ void __launch_bounds__(128)
attn_mma(const __half* __restrict__ qkv, __half* __restrict__ ctx)
{
    extern __shared__ __half smh[];
    __half* Qsh = smh;
    __half* Ksh = smh + TILE_H;
    __half* Vsh = Ksh + 2 * TILE_H;

    const int bh = blockIdx.x;
    const int qb = gridDim.y - 1 - blockIdx.y;
    const int b = bh >> 4, h = bh & 15;
    const int tid = threadIdx.x, lane = tid & 31, w = tid >> 5;
    const int g = lane >> 2, t = lane & 3;
    const int lr = lane & 15, lc = (lane >> 4) * 8;
    const int br = lane & 7, bseg = lane >> 3;

    const __half* qbase = qkv + ((size_t)(b * SEQ + qb * 64)) * QKVN + h * HDIM;
    for (int i = tid; i < 64 * 8; i += 128) {
        int r = i >> 3, c = i & 7;
        *(uint4*)(Qsh + r * HP + c * 8) = *(const uint4*)(qbase + (size_t)r * QKVN + c * 8);
    }
    __syncthreads();

    uint32_t qf[4][4];
    #pragma unroll
    for (int kc = 0; kc < 4; kc++)
        ldsm_x4(qf[kc], smem_u32(Qsh + (w * 16 + lr) * HP + kc * 16 + lc));
    __syncthreads();

    float oacc[8][4];
    #pragma unroll
    for (int nt = 0; nt < 8; nt++)
        #pragma unroll
        for (int e = 0; e < 4; e++) oacc[nt][e] = 0.f;

    float m_lo = -INFINITY, m_hi = -INFINITY, l_lo = 0.f, l_hi = 0.f;
    const float scale = 0.125f;

    auto load_kv = [&](int kt, int st) {
        const __half* kb = qkv + ((size_t)(b * SEQ + kt * 64)) * QKVN + h * HDIM + EMB;
        const __half* vb = kb + EMB;
        __half* ks = Ksh + st * TILE_H;
        __half* vs = Vsh + st * TILE_H;
        for (int i = tid; i < 64 * 8; i += 128) {
            int r = i >> 3, c = i & 7;
            cp16(ks + r * HP + c * 8, kb + (size_t)r * QKVN + c * 8);
            cp16(vs + r * HP + c * 8, vb + (size_t)r * QKVN + c * 8);
        }
        asm volatile("cp.async.commit_group;" ::: "memory");
    };

    load_kv(0, 0);

    __half* Pw = Qsh + (w * 16) * HP;

    for (int kt = 0; kt <= qb; kt++) {
        int st = kt & 1;
        if (kt < qb) {
            load_kv(kt + 1, st ^ 1);
            asm volatile("cp.async.wait_group 1;" ::: "memory");
        } else {
            asm volatile("cp.async.wait_group 0;" ::: "memory");
        }
        __syncthreads();

        const __half* ks = Ksh + st * TILE_H;
        const __half* vs = Vsh + st * TILE_H;

        float sacc[8][4];
        #pragma unroll
        for (int nt = 0; nt < 8; nt++)
            #pragma unroll
            for (int e = 0; e < 4; e++) sacc[nt][e] = 0.f;
        #pragma unroll
        for (int kc = 0; kc < 4; kc++) {
            #pragma unroll
            for (int nb = 0; nb < 4; nb++) {
                uint32_t kf[4];
                ldsm_x4(kf, smem_u32(ks + (nb * 16 + (bseg >> 1) * 8 + br) * HP
                                        + kc * 16 + (bseg & 1) * 8));
                mma16(sacc[nb * 2],     qf[kc], kf);
                mma16(sacc[nb * 2 + 1], qf[kc], kf + 2);
            }
        }

        float tl = -INFINITY, th = -INFINITY;
        const int row_lo = w * 16 + g;
        const int row_hi = row_lo + 8;
        #pragma unroll
        for (int nt = 0; nt < 8; nt++) {
            float s0 = sacc[nt][0] * scale;
            float s1 = sacc[nt][1] * scale;
            float s2 = sacc[nt][2] * scale;
            float s3 = sacc[nt][3] * scale;
            if (kt == qb) {
                int c0 = nt * 8 + t * 2, c1 = c0 + 1;
                if (c0 > row_lo) s0 = -INFINITY;
                if (c1 > row_lo) s1 = -INFINITY;
                if (c0 > row_hi) s2 = -INFINITY;
                if (c1 > row_hi) s3 = -INFINITY;
            }
            sacc[nt][0] = s0; sacc[nt][1] = s1; sacc[nt][2] = s2; sacc[nt][3] = s3;
            tl = fmaxf(tl, fmaxf(s0, s1));
            th = fmaxf(th, fmaxf(s2, s3));
        }
        tl = fmaxf(tl, __shfl_xor_sync(0xffffffffu, tl, 1));
        tl = fmaxf(tl, __shfl_xor_sync(0xffffffffu, tl, 2));
        th = fmaxf(th, __shfl_xor_sync(0xffffffffu, th, 1));
        th = fmaxf(th, __shfl_xor_sync(0xffffffffu, th, 2));

        float mn_lo = fmaxf(m_lo, tl);
        float mn_hi = fmaxf(m_hi, th);
        float c_lo = __expf(m_lo - mn_lo);
        float c_hi = __expf(m_hi - mn_hi);

        float sl = 0.f, sh2 = 0.f;
        #pragma unroll
        for (int nt = 0; nt < 8; nt++) {
            float p0 = __expf(sacc[nt][0] - mn_lo);
            float p1 = __expf(sacc[nt][1] - mn_lo);
            float p2 = __expf(sacc[nt][2] - mn_hi);
            float p3 = __expf(sacc[nt][3] - mn_hi);
            sl += p0 + p1; sh2 += p2 + p3;
            int c = nt * 8 + t * 2;
            *(half2*)&Pw[g * HP + c]       = __floats2half2_rn(p0, p1);
            *(half2*)&Pw[(g + 8) * HP + c] = __floats2half2_rn(p2, p3);
        }
        sl  += __shfl_xor_sync(0xffffffffu, sl, 1);
        sl  += __shfl_xor_sync(0xffffffffu, sl, 2);
        sh2 += __shfl_xor_sync(0xffffffffu, sh2, 1);
        sh2 += __shfl_xor_sync(0xffffffffu, sh2, 2);
        l_lo = l_lo * c_lo + sl;
        l_hi = l_hi * c_hi + sh2;
        m_lo = mn_lo; m_hi = mn_hi;

        #pragma unroll
        for (int nt = 0; nt < 8; nt++) {
            oacc[nt][0] *= c_lo; oacc[nt][1] *= c_lo;
            oacc[nt][2] *= c_hi; oacc[nt][3] *= c_hi;
        }
        __syncwarp();

        #pragma unroll
        for (int kc = 0; kc < 4; kc++) {
            uint32_t pf[4];
            ldsm_x4(pf, smem_u32(Pw + lr * HP + kc * 16 + lc));
            #pragma unroll
            for (int nb = 0; nb < 4; nb++) {
                uint32_t vf[4];
                ldsm_x4t(vf, smem_u32(vs + (kc * 16 + (bseg & 1) * 8 + br) * HP
                                         + nb * 16 + (bseg >> 1) * 8));
                mma16(oacc[nb * 2],     pf, vf);
                mma16(oacc[nb * 2 + 1], pf, vf + 2);
            }
        }
        __syncthreads();
    }

    float inv_lo = 1.f / l_lo, inv_hi = 1.f / l_hi;
    __half* ob = ctx + ((size_t)(b * SEQ + qb * 64 + w * 16)) * EMB + h * HDIM;
    #pragma unroll
    for (int nt = 0; nt < 8; nt++) {
        int c = nt * 8 + t * 2;
        *(half2*)(ob + (size_t)g * EMB + c) =
            __floats2half2_rn(oacc[nt][0] * inv_lo, oacc[nt][1] * inv_lo);
        *(half2*)(ob + (size_t)(g + 8) * EMB + c) =
            __floats2half2_rn(oacc[nt][2] * inv_hi, oacc[nt][3] * inv_hi);
    }
}

// ----------------------------------------------------------------------------
// Launch
// ----------------------------------------------------------------------------
extern "C" void kernel_launch(void* const* d_in, const int* in_sizes, int n_in,
                              void* d_out, int out_size)
{
    const float* x    = (const float*)d_in[0];
    const float* Wq   = (const float*)d_in[1];
    const float* Wk   = (const float*)d_in[2];
    const float* Wv   = (const float*)d_in[3];
    const float* Wo   = (const float*)d_in[4];
    const float* bo   = (const float*)d_in[5];
    const float* W1   = (const float*)d_in[6];
    const float* b1   = (const float*)d_in[7];
    const float* W2   = (const float*)d_in[8];
    const float* b2   = (const float*)d_in[9];
    const float* ln1s = (const float*)d_in[10];
    const float* ln1b = (const float*)d_in[11];
    const float* ln2s = (const float*)d_in[12];
    const float* ln2b = (const float*)d_in[13];
    float* out = (float*)d_out;

    __half *h_p, *qkv_p, *ctx_p, *ff_p, *wqkv_p, *wo_p, *w1_p, *w2_p;
    float *x1_p;
    cudaGetSymbolAddress((void**)&h_p,    g_h);
    cudaGetSymbolAddress((void**)&qkv_p,  g_qkv);
    cudaGetSymbolAddress((void**)&ctx_p,  g_ctx);
    cudaGetSymbolAddress((void**)&x1_p,   g_x1);
    cudaGetSymbolAddress((void**)&ff_p,   g_ff);
    cudaGetSymbolAddress((void**)&wqkv_p, g_wqkv);
    cudaGetSymbolAddress((void**)&wo_p,   g_wo);
    cudaGetSymbolAddress((void**)&w1_p,   g_w1);
    cudaGetSymbolAddress((void**)&w2_p,   g_w2);

    cudaFuncSetAttribute(gemm_mma, cudaFuncAttributeMaxDynamicSharedMemorySize, GEMM_SMEM);
    cudaFuncSetAttribute(attn_mma, cudaFuncAttributeMaxDynamicSharedMemorySize, ATTN_SMEM);

    // weight prep (fp32 -> fp16)
    pack_qkv_h<<<(EMB * EMB / 8 + 255) / 256, 256>>>(Wq, Wk, Wv, wqkv_p);
    tohalf<<<(EMB * EMB / 16 + 255) / 256, 256>>>(Wo, wo_p, EMB * EMB);
    tohalf<<<(EMB * FFDIM / 16 + 255) / 256, 256>>>(W1, w1_p, EMB * FFDIM);
    tohalf<<<(EMB * FFDIM / 16 + 255) / 256, 256>>>(W2, w2_p, FFDIM * EMB);

    // 1) LN1 -> fp16
    ln_kernel<<<MROWS, 256>>>(x, ln1s, ln1b, h_p);

    dim3 gqkv(QKVN / 128, MROWS / BM);     // (24, 16)
    dim3 g1024(EMB / 128, MROWS / BM);     // (8, 16)
    dim3 g4096(FFDIM / 128, MROWS / BM);   // (32, 16)

    // 2) fused QKV projection -> fp16
    gemm_mma<<<gqkv, 512, GEMM_SMEM>>>(h_p, wqkv_p, nullptr, nullptr, qkv_p, QKVN, EMB, 2);

    // 3) causal attention -> fp16 ctx
    dim3 attn_grid(BATCH * HEADS, SEQ / 64);
    attn_mma<<<attn_grid, 128, ATTN_SMEM>>>(qkv_p, ctx_p);

    // 4) x1 = x + ctx @ Wo + bo  (fp32 out)
    gemm_mma<<<g1024, 512, GEMM_SMEM>>>(ctx_p, wo_p, bo, x, x1_p, EMB, EMB, 0);

    // 5) LN2 -> fp16
    ln_kernel<<<MROWS, 256>>>(x1_p, ln2s, ln2b, h_p);

    // 6) ff = gelu(h @ W1 + b1) -> fp16
    gemm_mma<<<g4096, 512, GEMM_SMEM>>>(h_p, w1_p, b1, nullptr, ff_p, FFDIM, EMB, 3);

    // 7) out = x1 + ff @ W2 + b2  (fp32 out)
    gemm_mma<<<g1024, 512, GEMM_SMEM>>>(ff_p, w2_p, b2, x1_p, out, EMB, FFDIM, 0);
}

// round 10
// speedup vs baseline: 7.1414x; 1.0218x over previous
#include <cuda_runtime.h>
#include <cuda_fp16.h>
#include <math.h>
#include <stdint.h>

#define BATCH 2
#define SEQ   2048
#define EMB   1024
#define HEADS 16
#define HDIM  64
#define FFDIM 4096
#define MROWS (BATCH * SEQ)   // 4096
#define QKVN  (3 * EMB)       // 3072

// ----------------------------------------------------------------------------
// Scratch (device globals — no runtime allocation allowed)
// ----------------------------------------------------------------------------
__device__ __half g_h   [MROWS * EMB];
__device__ __half g_qkv [MROWS * QKVN];
__device__ __half g_ctx [MROWS * EMB];
__device__ float  g_x1  [MROWS * EMB];
__device__ __half g_ff  [MROWS * FFDIM];
__device__ __half g_wqkv[EMB * QKVN];
__device__ __half g_wo  [EMB * EMB];
__device__ __half g_w1  [EMB * FFDIM];
__device__ __half g_w2  [FFDIM * EMB];

// ----------------------------------------------------------------------------
// Helpers
// ----------------------------------------------------------------------------
__device__ __forceinline__ uint32_t smem_u32(const void* p) {
    uint32_t a;
    asm("{ .reg .u64 t; cvta.to.shared.u64 t, %1; cvt.u32.u64 %0, t; }" : "=r"(a) : "l"(p));
    return a;
}
__device__ __forceinline__ void cp16(void* dst, const void* src) {
    asm volatile("cp.async.cg.shared.global [%0], [%1], 16;"
                 :: "r"(smem_u32(dst)), "l"(src) : "memory");
}
// gelu_tanh == x * sigmoid(2u), u = c*(x + 0.044715 x^3). Exact same function,
// ~6 ops instead of ~30 (tanhf). Limits: x->+inf => exp->0 => x; x->-inf => 0.
__device__ __forceinline__ float gelu_tanh(float x) {
    float u2 = 1.5957691216f * x * (1.0f + 0.044715f * x * x);   // = 2u
    return __fdividef(x, 1.0f + __expf(-u2));
}
__device__ __forceinline__ void ldsm_x4(uint32_t* r, uint32_t addr) {
    asm volatile("ldmatrix.sync.aligned.m8n8.x4.shared.b16 {%0,%1,%2,%3}, [%4];"
                 : "=r"(r[0]), "=r"(r[1]), "=r"(r[2]), "=r"(r[3]) : "r"(addr));
}
__device__ __forceinline__ void ldsm_x4t(uint32_t* r, uint32_t addr) {
    asm volatile("ldmatrix.sync.aligned.m8n8.x4.trans.shared.b16 {%0,%1,%2,%3}, [%4];"
                 : "=r"(r[0]), "=r"(r[1]), "=r"(r[2]), "=r"(r[3]) : "r"(addr));
}
__device__ __forceinline__ void mma16(float* c, const uint32_t* a, const uint32_t* b) {
    asm volatile(
        "mma.sync.aligned.m16n8k16.row.col.f32.f16.f16.f32 "
        "{%0,%1,%2,%3}, {%4,%5,%6,%7}, {%8,%9}, {%0,%1,%2,%3};"
        : "+f"(c[0]), "+f"(c[1]), "+f"(c[2]), "+f"(c[3])
        : "r"(a[0]), "r"(a[1]), "r"(a[2]), "r"(a[3]), "r"(b[0]), "r"(b[1]));
}

// ----------------------------------------------------------------------------
// LayerNorm: fp32 in, fp16 out
// ----------------------------------------------------------------------------
__inline__ __device__ float warp_sum(float v) {
    #pragma unroll
    for (int o = 16; o > 0; o >>= 1) v += __shfl_xor_sync(0xffffffffu, v, o);
    return v;
}
__global__ void ln_kernel(const float* __restrict__ x,
                          const float* __restrict__ scale,
                          const float* __restrict__ shift,
                          __half* __restrict__ out)
{
    __shared__ float ssum[8], ssq[8];
    int row = blockIdx.x;
    int t = threadIdx.x;
    const float4* xr = (const float4*)(x + (size_t)row * EMB);
    float4 v = xr[t];
    float s  = v.x + v.y + v.z + v.w;
    float sq = v.x * v.x + v.y * v.y + v.z * v.z + v.w * v.w;
    float ws  = warp_sum(s);
    float wsq = warp_sum(sq);
    int lane = t & 31, wid = t >> 5;
    if (lane == 0) { ssum[wid] = ws; ssq[wid] = wsq; }
    __syncthreads();
    float tot = 0.f, totsq = 0.f;
    #pragma unroll
    for (int i = 0; i < 8; i++) { tot += ssum[i]; totsq += ssq[i]; }
    float mean = tot * (1.0f / EMB);
    float var  = totsq * (1.0f / EMB) - mean * mean;
    float inv  = rsqrtf(var + 1e-5f);
    float4 sc = ((const float4*)scale)[t];
    float4 sh = ((const float4*)shift)[t];
    __half* op = out + (size_t)row * EMB + t * 4;
    *(half2*)op       = __floats2half2_rn(sc.x * (v.x - mean) * inv + sh.x,
                                          sc.y * (v.y - mean) * inv + sh.y);
    *(half2*)(op + 2) = __floats2half2_rn(sc.z * (v.z - mean) * inv + sh.z,
                                          sc.w * (v.w - mean) * inv + sh.w);
}

// ----------------------------------------------------------------------------
// Weight prep: fp32 -> fp16 (and QKV pack)
// ----------------------------------------------------------------------------
__global__ void tohalf(const float* __restrict__ in, __half* __restrict__ out, int n)
{
    int i = (blockIdx.x * blockDim.x + threadIdx.x) * 8;
    if (i < n) {
        float4 a = *(const float4*)(in + i);
        float4 b = *(const float4*)(in + i + 4);
        half2 h0 = __floats2half2_rn(a.x, a.y);
        half2 h1 = __floats2half2_rn(a.z, a.w);
        half2 h2 = __floats2half2_rn(b.x, b.y);
        half2 h3 = __floats2half2_rn(b.z, b.w);
        uint4 u;
        u.x = *(uint32_t*)&h0; u.y = *(uint32_t*)&h1;
        u.z = *(uint32_t*)&h2; u.w = *(uint32_t*)&h3;
        *(uint4*)(out + i) = u;
    }
}
__global__ void pack_qkv_h(const float* __restrict__ Wq, const float* __restrict__ Wk,
                           const float* __restrict__ Wv, __half* __restrict__ out)
{
    int i = (blockIdx.x * blockDim.x + threadIdx.x) * 8;   // over EMB*EMB
    int k = i >> 10;
    int n = i & 1023;
    __half* o = out + (size_t)k * QKVN + n;
    const float* srcs[3] = {Wq + i, Wk + i, Wv + i};
    #pragma unroll
    for (int m = 0; m < 3; m++) {
        float4 a = *(const float4*)(srcs[m]);
        float4 b = *(const float4*)(srcs[m] + 4);
        half2 h0 = __floats2half2_rn(a.x, a.y), h1 = __floats2half2_rn(a.z, a.w);
        half2 h2 = __floats2half2_rn(b.x, b.y), h3 = __floats2half2_rn(b.z, b.w);
        uint4 u;
        u.x = *(uint32_t*)&h0; u.y = *(uint32_t*)&h1;
        u.z = *(uint32_t*)&h2; u.w = *(uint32_t*)&h3;
        *(uint4*)(o + m * EMB) = u;
    }
}

// ----------------------------------------------------------------------------
// fp16 mma.sync GEMM, BK=64, 3-stage cp.async pipeline.
// CTA 256x128, 512 threads (16 warps, 4Mx4N), warp tile 64x32.
// flags: 1 = gelu, 2 = fp16 output
// ----------------------------------------------------------------------------
#define BK 64
#define BM 256
#define AP 72
#define BPH 136
#define NSTG 3
#define A_STGH (BM * AP)
#define B_STGH (BK * BPH)
#define STG_H (A_STGH + B_STGH)
#define GEMM_SMEM (NSTG * STG_H * 2)

__global__ void __launch_bounds__(512, 1)
gemm_mma(const __half* __restrict__ A, const __half* __restrict__ B,
         const float* __restrict__ bias, const float* __restrict__ res,
         void* __restrict__ Cout, int N, int K, int flags)
{
    extern __shared__ __half smh[];

    const int tid  = threadIdx.x;
    const int lane = tid & 31;
    const int warp = tid >> 5;
    const int wm   = warp & 3;
    const int wn   = warp >> 2;
    const int brow = blockIdx.y * BM;
    const int bcol = blockIdx.x * 128;
    const int g = lane >> 2, t = lane & 3;

    float acc[4][4][4];
    #pragma unroll
    for (int mt = 0; mt < 4; mt++)
        #pragma unroll
        for (int nt = 0; nt < 4; nt++)
            #pragma unroll
            for (int e = 0; e < 4; e++) acc[mt][nt][e] = 0.f;

    const int nk = K / BK;

    auto load_stage = [&](int st, int k0) {
        __half* as = smh + st * STG_H;
        __half* bs = as + A_STGH;
        #pragma unroll
        for (int i = 0; i < 4; i++) {
            int id = tid + i * 512;
            int row = id >> 3, c = (id & 7) * 8;
            cp16(as + row * AP + c, A + (size_t)(brow + row) * K + k0 + c);
        }
        #pragma unroll
        for (int i = 0; i < 2; i++) {
            int id = tid + i * 512;
            int row = id >> 4, c = (id & 15) * 8;
            cp16(bs + row * BPH + c, B + (size_t)(k0 + row) * N + bcol + c);
        }
        asm volatile("cp.async.commit_group;" ::: "memory");
    };

    load_stage(0, 0);
    load_stage(1, BK);

    const int lr = lane & 15;
    const int lc = (lane >> 4) * 8;
    const int br = lane & 7;
    const int bseg = lane >> 3;

    int st = 0;
    for (int kt = 0; kt < nk; kt++) {
        asm volatile("cp.async.wait_group 1;" ::: "memory");
        __syncthreads();

        int nxt = kt + NSTG - 1;
        int nst = st + NSTG - 1; if (nst >= NSTG) nst -= NSTG;
        if (nxt < nk) load_stage(nst, nxt * BK);
        else asm volatile("cp.async.commit_group;" ::: "memory");

        const __half* as = smh + st * STG_H + (wm * 64) * AP;
        const __half* bs = smh + st * STG_H + A_STGH + wn * 32;

        #pragma unroll
        for (int ks = 0; ks < 4; ks++) {
            const int k = ks * 16;
            uint32_t af[4][4];
            #pragma unroll
            for (int mt = 0; mt < 4; mt++)
                ldsm_x4(af[mt], smem_u32(as + (mt * 16 + lr) * AP + k + lc));
            #pragma unroll
            for (int nbh = 0; nbh < 2; nbh++) {
                uint32_t bf[4];
                ldsm_x4t(bf, smem_u32(bs + (k + (bseg & 1) * 8 + br) * BPH
                                         + nbh * 16 + (bseg >> 1) * 8));
                #pragma unroll
                for (int mt = 0; mt < 4; mt++) {
                    mma16(acc[mt][nbh * 2],     af[mt], bf);
                    mma16(acc[mt][nbh * 2 + 1], af[mt], bf + 2);
                }
            }
        }
        if (++st == NSTG) st = 0;
    }

    // ---------------- epilogue ----------------
    #pragma unroll
    for (int mt = 0; mt < 4; mt++) {
        int r0 = brow + wm * 64 + mt * 16 + g;
        #pragma unroll
        for (int nt = 0; nt < 4; nt++) {
            int col = bcol + wn * 32 + nt * 8 + t * 2;
            float v0 = acc[mt][nt][0], v1 = acc[mt][nt][1];
            float v2 = acc[mt][nt][2], v3 = acc[mt][nt][3];
            if (bias) {
                float b0 = __ldg(bias + col), b1 = __ldg(bias + col + 1);
                v0 += b0; v1 += b1; v2 += b0; v3 += b1;
            }
            if (flags & 1) {
                v0 = gelu_tanh(v0); v1 = gelu_tanh(v1);
                v2 = gelu_tanh(v2); v3 = gelu_tanh(v3);
            }
            size_t i0 = (size_t)r0 * N + col;
            size_t i1 = (size_t)(r0 + 8) * N + col;
            if (res) {
                float2 r0v = *(const float2*)(res + i0);
                float2 r1v = *(const float2*)(res + i1);
                v0 += r0v.x; v1 += r0v.y; v2 += r1v.x; v3 += r1v.y;
            }
            if (flags & 2) {
                *(half2*)((__half*)Cout + i0) = __floats2half2_rn(v0, v1);
                *(half2*)((__half*)Cout + i1) = __floats2half2_rn(v2, v3);
            } else {
                *(float2*)((float*)Cout + i0) = make_float2(v0, v1);
                *(float2*)((float*)Cout + i1) = make_float2(v2, v3);
            }
        }
    }
}

// ----------------------------------------------------------------------------
// fp16 tensor-core causal flash attention
// ----------------------------------------------------------------------------
#define HP 72
#define TILE_H (64 * HP)
#define ATTN_SMEM (5 * TILE_H * 2)

__global__ void __launch_bounds__(128)
attn_mma(const __half* __restrict__ qkv, __half* __restrict__ ctx)
{
    extern __shared__ __half smh[];
    __half* Qsh = smh;
    __half* Ksh = smh + TILE_H;
    __half* Vsh = Ksh + 2 * TILE_H;

    const int bh = blockIdx.x;
    const int qb = gridDim.y - 1 - blockIdx.y;
    const int b = bh >> 4, h = bh & 15;
    const int tid = threadIdx.x, lane = tid & 31, w = tid >> 5;
    const int g = lane >> 2, t = lane & 3;
    const int lr = lane & 15, lc = (lane >> 4) * 8;
    const int br = lane & 7, bseg = lane >> 3;

    const __half* qbase = qkv + ((size_t)(b * SEQ + qb * 64)) * QKVN + h * HDIM;
    for (int i = tid; i < 64 * 8; i += 128) {
        int r = i >> 3, c = i & 7;
        *(uint4*)(Qsh + r * HP + c * 8) = *(const uint4*)(qbase + (size_t)r * QKVN + c * 8);
    }
    __syncthreads();

    uint32_t qf[4][4];
    #pragma unroll
    for (int kc = 0; kc < 4; kc++)
        ldsm_x4(qf[kc], smem_u32(Qsh + (w * 16 + lr) * HP + kc * 16 + lc));
    __syncthreads();

    float oacc[8][4];
    #pragma unroll
    for (int nt = 0; nt < 8; nt++)
        #pragma unroll
        for (int e = 0; e < 4; e++) oacc[nt][e] = 0.f;

    float m_lo = -INFINITY, m_hi = -INFINITY, l_lo = 0.f, l_hi = 0.f;
    const float scale = 0.125f;

    auto load_kv = [&](int kt, int st) {
        const __half* kb = qkv + ((size_t)(b * SEQ + kt * 64)) * QKVN + h * HDIM + EMB;
        const __half* vb = kb + EMB;
        __half* ks = Ksh + st * TILE_H;
        __half* vs = Vsh + st * TILE_H;
        for (int i = tid; i < 64 * 8; i += 128) {
            int r = i >> 3, c = i & 7;
            cp16(ks + r * HP + c * 8, kb + (size_t)r * QKVN + c * 8);
            cp16(vs + r * HP + c * 8, vb + (size_t)r * QKVN + c * 8);
        }
        asm volatile("cp.async.commit_group;" ::: "memory");
    };

    load_kv(0, 0);

    __half* Pw = Qsh + (w * 16) * HP;

    for (int kt = 0; kt <= qb; kt++) {
        int st = kt & 1;
        if (kt < qb) {
            load_kv(kt + 1, st ^ 1);
            asm volatile("cp.async.wait_group 1;" ::: "memory");
        } else {
            asm volatile("cp.async.wait_group 0;" ::: "memory");
        }
        __syncthreads();

        const __half* ks = Ksh + st * TILE_H;
        const __half* vs = Vsh + st * TILE_H;

        float sacc[8][4];
        #pragma unroll
        for (int nt = 0; nt < 8; nt++)
            #pragma unroll
            for (int e = 0; e < 4; e++) sacc[nt][e] = 0.f;
        #pragma unroll
        for (int kc = 0; kc < 4; kc++) {
            #pragma unroll
            for (int nb = 0; nb < 4; nb++) {
                uint32_t kf[4];
                ldsm_x4(kf, smem_u32(ks + (nb * 16 + (bseg >> 1) * 8 + br) * HP
                                        + kc * 16 + (bseg & 1) * 8));
                mma16(sacc[nb * 2],     qf[kc], kf);
                mma16(sacc[nb * 2 + 1], qf[kc], kf + 2);
            }
        }

        float tl = -INFINITY, th = -INFINITY;
        const int row_lo = w * 16 + g;
        const int row_hi = row_lo + 8;
        #pragma unroll
        for (int nt = 0; nt < 8; nt++) {
            float s0 = sacc[nt][0] * scale;
            float s1 = sacc[nt][1] * scale;
            float s2 = sacc[nt][2] * scale;
            float s3 = sacc[nt][3] * scale;
            if (kt == qb) {
                int c0 = nt * 8 + t * 2, c1 = c0 + 1;
                if (c0 > row_lo) s0 = -INFINITY;
                if (c1 > row_lo) s1 = -INFINITY;
                if (c0 > row_hi) s2 = -INFINITY;
                if (c1 > row_hi) s3 = -INFINITY;
            }
            sacc[nt][0] = s0; sacc[nt][1] = s1; sacc[nt][2] = s2; sacc[nt][3] = s3;
            tl = fmaxf(tl, fmaxf(s0, s1));
            th = fmaxf(th, fmaxf(s2, s3));
        }
        tl = fmaxf(tl, __shfl_xor_sync(0xffffffffu, tl, 1));
        tl = fmaxf(tl, __shfl_xor_sync(0xffffffffu, tl, 2));
        th = fmaxf(th, __shfl_xor_sync(0xffffffffu, th, 1));
        th = fmaxf(th, __shfl_xor_sync(0xffffffffu, th, 2));

        float mn_lo = fmaxf(m_lo, tl);
        float mn_hi = fmaxf(m_hi, th);
        float c_lo = __expf(m_lo - mn_lo);
        float c_hi = __expf(m_hi - mn_hi);

        float sl = 0.f, sh2 = 0.f;
        #pragma unroll
        for (int nt = 0; nt < 8; nt++) {
            float p0 = __expf(sacc[nt][0] - mn_lo);
            float p1 = __expf(sacc[nt][1] - mn_lo);
            float p2 = __expf(sacc[nt][2] - mn_hi);
            float p3 = __expf(sacc[nt][3] - mn_hi);
            sl += p0 + p1; sh2 += p2 + p3;
            int c = nt * 8 + t * 2;
            *(half2*)&Pw[g * HP + c]       = __floats2half2_rn(p0, p1);
            *(half2*)&Pw[(g + 8) * HP + c] = __floats2half2_rn(p2, p3);
        }
        sl  += __shfl_xor_sync(0xffffffffu, sl, 1);
        sl  += __shfl_xor_sync(0xffffffffu, sl, 2);
        sh2 += __shfl_xor_sync(0xffffffffu, sh2, 1);
        sh2 += __shfl_xor_sync(0xffffffffu, sh2, 2);
        l_lo = l_lo * c_lo + sl;
        l_hi = l_hi * c_hi + sh2;
        m_lo = mn_lo; m_hi = mn_hi;

        #pragma unroll
        for (int nt = 0; nt < 8; nt++) {
            oacc[nt][0] *= c_lo; oacc[nt][1] *= c_lo;
            oacc[nt][2] *= c_hi; oacc[nt][3] *= c_hi;
        }
        __syncwarp();

        #pragma unroll
        for (int kc = 0; kc < 4; kc++) {
            uint32_t pf[4];
            ldsm_x4(pf, smem_u32(Pw + lr * HP + kc * 16 + lc));
            #pragma unroll
            for (int nb = 0; nb < 4; nb++) {
                uint32_t vf[4];
                ldsm_x4t(vf, smem_u32(vs + (kc * 16 + (bseg & 1) * 8 + br) * HP
                                         + nb * 16 + (bseg >> 1) * 8));
                mma16(oacc[nb * 2],     pf, vf);
                mma16(oacc[nb * 2 + 1], pf, vf + 2);
            }
        }
        __syncthreads();
    }

    float inv_lo = 1.f / l_lo, inv_hi = 1.f / l_hi;
    __half* ob = ctx + ((size_t)(b * SEQ + qb * 64 + w * 16)) * EMB + h * HDIM;
    #pragma unroll
    for (int nt = 0; nt < 8; nt++) {
        int c = nt * 8 + t * 2;
        *(half2*)(ob + (size_t)g * EMB + c) =
            __floats2half2_rn(oacc[nt][0] * inv_lo, oacc[nt][1] * inv_lo);
        *(half2*)(ob + (size_t)(g + 8) * EMB + c) =
            __floats2half2_rn(oacc[nt][2] * inv_hi, oacc[nt][3] * inv_hi);
    }
}

// ----------------------------------------------------------------------------
// Launch — weight prep forked onto a side stream, overlapped with LN1/QKV/attn
// ----------------------------------------------------------------------------
extern "C" void kernel_launch(void* const* d_in, const int* in_sizes, int n_in,
                              void* d_out, int out_size)
{
    const float* x    = (const float*)d_in[0];
    const float* Wq   = (const float*)d_in[1];
    const float* Wk   = (const float*)d_in[2];
    const float* Wv   = (const float*)d_in[3];
    const float* Wo   = (const float*)d_in[4];
    const float* bo   = (const float*)d_in[5];
    const float* W1   = (const float*)d_in[6];
    const float* b1   = (const float*)d_in[7];
    const float* W2   = (const float*)d_in[8];
    const float* b2   = (const float*)d_in[9];
    const float* ln1s = (const float*)d_in[10];
    const float* ln1b = (const float*)d_in[11];
    const float* ln2s = (const float*)d_in[12];
    const float* ln2b = (const float*)d_in[13];
    float* out = (float*)d_out;

    __half *h_p, *qkv_p, *ctx_p, *ff_p, *wqkv_p, *wo_p, *w1_p, *w2_p;
    float *x1_p;
    cudaGetSymbolAddress((void**)&h_p,    g_h);
    cudaGetSymbolAddress((void**)&qkv_p,  g_qkv);
    cudaGetSymbolAddress((void**)&ctx_p,  g_ctx);
    cudaGetSymbolAddress((void**)&x1_p,   g_x1);
    cudaGetSymbolAddress((void**)&ff_p,   g_ff);
    cudaGetSymbolAddress((void**)&wqkv_p, g_wqkv);
    cudaGetSymbolAddress((void**)&wo_p,   g_wo);
    cudaGetSymbolAddress((void**)&w1_p,   g_w1);
    cudaGetSymbolAddress((void**)&w2_p,   g_w2);

    cudaFuncSetAttribute(gemm_mma, cudaFuncAttributeMaxDynamicSharedMemorySize, GEMM_SMEM);
    cudaFuncSetAttribute(attn_mma, cudaFuncAttributeMaxDynamicSharedMemorySize, ATTN_SMEM);

    // fork a side stream for weight prep (capture-legal event fork/join)
    cudaStream_t s2;
    cudaStreamCreateWithFlags(&s2, cudaStreamNonBlocking);
    cudaEvent_t evRoot, evQKVw, evW;
    cudaEventCreateWithFlags(&evRoot,  cudaEventDisableTiming);
    cudaEventCreateWithFlags(&evQKVw,  cudaEventDisableTiming);
    cudaEventCreateWithFlags(&evW,     cudaEventDisableTiming);

    cudaEventRecord(evRoot, 0);
    cudaStreamWaitEvent(s2, evRoot, 0);

    // side stream: weight prep
    pack_qkv_h<<<(EMB * EMB / 8 + 255) / 256, 256, 0, s2>>>(Wq, Wk, Wv, wqkv_p);
    cudaEventRecord(evQKVw, s2);
    tohalf<<<(EMB * EMB / 8 + 255) / 256, 256, 0, s2>>>(Wo, wo_p, EMB * EMB);
    tohalf<<<(EMB * FFDIM / 8 + 255) / 256, 256, 0, s2>>>(W1, w1_p, EMB * FFDIM);
    tohalf<<<(EMB * FFDIM / 8 + 255) / 256, 256, 0, s2>>>(W2, w2_p, FFDIM * EMB);
    cudaEventRecord(evW, s2);

    // main stream
    // 1) LN1 -> fp16 (overlaps pack_qkv)
    ln_kernel<<<MROWS, 256>>>(x, ln1s, ln1b, h_p);

    dim3 gqkv(QKVN / 128, MROWS / BM);
    dim3 g1024(EMB / 128, MROWS / BM);
    dim3 g4096(FFDIM / 128, MROWS / BM);

    // 2) fused QKV projection (needs wqkv)
    cudaStreamWaitEvent(0, evQKVw, 0);
    gemm_mma<<<gqkv, 512, GEMM_SMEM>>>(h_p, wqkv_p, nullptr, nullptr, qkv_p, QKVN, EMB, 2);

    // 3) causal attention -> fp16 ctx (Wo/W1/W2 tohalf overlaps here)
    dim3 attn_grid(BATCH * HEADS, SEQ / 64);
    attn_mma<<<attn_grid, 128, ATTN_SMEM>>>(qkv_p, ctx_p);

    // 4) x1 = x + ctx @ Wo + bo  (needs wo/w1/w2 done)
    cudaStreamWaitEvent(0, evW, 0);
    gemm_mma<<<g1024, 512, GEMM_SMEM>>>(ctx_p, wo_p, bo, x, x1_p, EMB, EMB, 0);

    // 5) LN2 -> fp16
    ln_kernel<<<MROWS, 256>>>(x1_p, ln2s, ln2b, h_p);

    // 6) ff = gelu(h @ W1 + b1) -> fp16
    gemm_mma<<<g4096, 512, GEMM_SMEM>>>(h_p, w1_p, b1, nullptr, ff_p, FFDIM, EMB, 3);

    // 7) out = x1 + ff @ W2 + b2  (fp32 out)
    gemm_mma<<<g1024, 512, GEMM_SMEM>>>(ff_p, w2_p, b2, x1_p, out, EMB, FFDIM, 0);
}